// round 5
// baseline (speedup 1.0000x reference)
#include <cuda_runtime.h>
#include <cuda_fp16.h>
#include <cstdint>
#include <math.h>

// Problem shape
#define BB 64
#define TT 128
#define DD 512
#define HH 2048

// Intermediate h = gelu(x@W1+b1), layout [t][m][hidx] (fp32, 64MB)
__device__ float g_h[(size_t)TT * BB * HH];

static constexpr int SA = 40;   // padded SMEM row stride in fp16 (80 B, ldsm conflict-free)
static constexpr int NT = 256;  // 8 warps

// dynamic SMEM stage layout (bytes)
static constexpr int A_HI = 0;            // act  [64 m][32 k] fp16 hi  (5120)
static constexpr int A_LO = 5120;         // act lo                      (5120)
static constexpr int W_HI = 10240;        // wgt  [128 n][32 k] fp16    (10240)
static constexpr int STAGE = 20480;
static constexpr int SMEM_BYTES = 2 * STAGE;  // 40960

// ───────────── helpers ─────────────
__device__ __forceinline__ uint32_t smem_u32(const void* p) {
    uint32_t a;
    asm("{ .reg .u64 t; cvta.to.shared.u64 t, %1; cvt.u32.u64 %0, t; }" : "=r"(a) : "l"(p));
    return a;
}
__device__ __forceinline__ void ldsm_x4(uint32_t* r, uint32_t addr) {
    asm volatile("ldmatrix.sync.aligned.m8n8.x4.shared.b16 {%0,%1,%2,%3}, [%4];"
                 : "=r"(r[0]), "=r"(r[1]), "=r"(r[2]), "=r"(r[3]) : "r"(addr));
}
__device__ __forceinline__ void mma16816(float* c, const uint32_t* a, uint32_t b0, uint32_t b1) {
    asm volatile("mma.sync.aligned.m16n8k16.row.col.f32.f16.f16.f32 "
                 "{%0,%1,%2,%3}, {%4,%5,%6,%7}, {%8,%9}, {%0,%1,%2,%3};"
                 : "+f"(c[0]), "+f"(c[1]), "+f"(c[2]), "+f"(c[3])
                 : "r"(a[0]), "r"(a[1]), "r"(a[2]), "r"(a[3]), "r"(b0), "r"(b1));
}
// split two fp32 into packed fp16 hi-pair and lo-pair (x = low half = smaller k)
__device__ __forceinline__ void split2(float x, float y, uint32_t& hi, uint32_t& lo) {
    __half hx = __float2half_rn(x);
    __half hy = __float2half_rn(y);
    __half lx = __float2half_rn(x - __half2float(hx));
    __half ly = __float2half_rn(y - __half2float(hy));
    hi = ((uint32_t)(*reinterpret_cast<uint16_t*>(&hy)) << 16) | *reinterpret_cast<uint16_t*>(&hx);
    lo = ((uint32_t)(*reinterpret_cast<uint16_t*>(&ly)) << 16) | *reinterpret_cast<uint16_t*>(&lx);
}
// round two fp32 to a packed fp16 pair
__device__ __forceinline__ uint32_t pack_h2(float x, float y) {
    __half2 t = __floats2half2_rn(x, y);
    return *reinterpret_cast<uint32_t*>(&t);
}

// ───────────── FFN GEMM via mma.sync (exact-in-A fp16 split, 2 passes, pipelined) ─────────────
// Per CTA: token t, output block n0..n0+127, full batch m=0..63.
//   Out[t*OTS + m*OMS + n0+n] = act( sum_k Act[m,k] * W[t][k, n0+n] + bias[t, n0+n] )
template <int K, int NFULL, int ATS, int AMS, int OTS, int OMS, bool DOGELU>
__global__ void __launch_bounds__(NT, 3)
ffn_mma(const float* __restrict__ W, const float* __restrict__ Act,
        const float* __restrict__ bias, float* __restrict__ Out)
{
    extern __shared__ char smem[];
    const int t    = blockIdx.y;
    const int n0   = blockIdx.x * 128;
    const int tid  = threadIdx.x;
    const int wid  = tid >> 5;
    const int lane = tid & 31;
    const uint32_t sbase = smem_u32(smem);

    const float* At = Act + (size_t)t * ATS;
    const float* Wt = W + (size_t)t * K * NFULL + n0;

    // warp tile: m32 x n32
    const int mw = (wid >> 2) * 32;
    const int nwarp = (wid & 3) * 32;

    // ldmatrix per-lane byte offsets
    const uint32_t aLaneOff = (uint32_t)(((lane & 15) * SA + (lane >> 4) * 8) * 2);
    const uint32_t bLaneOff = (uint32_t)(((((lane >> 4) << 3) + (lane & 7)) * SA +
                                          (((lane >> 3) & 1) * 8) ) * 2);

    // staging assignments
    const int am0 = tid >> 3;               // act: idx 0..255 -> m, k4
    const int ak0 = (tid & 7) * 4;
    const int am1 = (NT + tid) >> 3;        // idx 256..511
    const int ak1 = ((NT + tid) & 7) * 4;
    const int wn  = tid & 127;              // weights: column n, k-group of 16 rows
    const int wkg = tid >> 7;               // 0/1

    float acc[32];                          // [mf][np][atom][4]
#pragma unroll
    for (int i = 0; i < 32; i++) acc[i] = 0.0f;

    float4 pa0, pa1;
    float pw[16];

    auto LOADS = [&](int c) {
        pa0 = *reinterpret_cast<const float4*>(At + (size_t)am0 * AMS + c * 32 + ak0);
        pa1 = *reinterpret_cast<const float4*>(At + (size_t)am1 * AMS + c * 32 + ak1);
        const float* p = Wt + (size_t)(c * 32 + wkg * 16) * NFULL + wn;
#pragma unroll
        for (int r = 0; r < 16; r++) pw[r] = p[(size_t)r * NFULL];
    };

    auto STORE = [&](int s) {
        char* st = smem + s * STAGE;
        {
            uint32_t h0, l0, h1, l1;
            split2(pa0.x, pa0.y, h0, l0); split2(pa0.z, pa0.w, h1, l1);
            int bo = am0 * (SA * 2) + ak0 * 2;
            *reinterpret_cast<uint2*>(st + A_HI + bo) = make_uint2(h0, h1);
            *reinterpret_cast<uint2*>(st + A_LO + bo) = make_uint2(l0, l1);
            split2(pa1.x, pa1.y, h0, l0); split2(pa1.z, pa1.w, h1, l1);
            bo = am1 * (SA * 2) + ak1 * 2;
            *reinterpret_cast<uint2*>(st + A_HI + bo) = make_uint2(h0, h1);
            *reinterpret_cast<uint2*>(st + A_LO + bo) = make_uint2(l0, l1);
        }
        {
            uint32_t h[8];
#pragma unroll
            for (int r = 0; r < 8; r++) h[r] = pack_h2(pw[2 * r], pw[2 * r + 1]);
            int bo = wn * (SA * 2) + wkg * 32;
            *reinterpret_cast<uint4*>(st + W_HI + bo)      = make_uint4(h[0], h[1], h[2], h[3]);
            *reinterpret_cast<uint4*>(st + W_HI + bo + 16) = make_uint4(h[4], h[5], h[6], h[7]);
        }
    };

    auto MMA = [&](int s) {
        const uint32_t ab = sbase + s * STAGE;
        const uint32_t aHi = ab + A_HI + mw * (SA * 2) + aLaneOff;
        const uint32_t aLo = ab + A_LO + mw * (SA * 2) + aLaneOff;
        const uint32_t bHi = ab + W_HI + nwarp * (SA * 2) + bLaneOff;
#pragma unroll
        for (int ks = 0; ks < 2; ks++) {
            uint32_t ah[2][4], al[2][4];
#pragma unroll
            for (int mf = 0; mf < 2; mf++) {
                ldsm_x4(ah[mf], aHi + mf * (16 * SA * 2) + ks * 32);
                ldsm_x4(al[mf], aLo + mf * (16 * SA * 2) + ks * 32);
            }
#pragma unroll
            for (int np = 0; np < 2; np++) {
                uint32_t bh[4];
                ldsm_x4(bh, bHi + np * (16 * SA * 2) + ks * 32);
#pragma unroll
                for (int mf = 0; mf < 2; mf++) {
                    float* c0 = acc + ((mf * 2 + np) * 2 + 0) * 4;
                    float* c1 = acc + ((mf * 2 + np) * 2 + 1) * 4;
                    mma16816(c0, ah[mf], bh[0], bh[1]);
                    mma16816(c1, ah[mf], bh[2], bh[3]);
                    mma16816(c0, al[mf], bh[0], bh[1]);
                    mma16816(c1, al[mf], bh[2], bh[3]);
                }
            }
        }
    };

    constexpr int NCHUNK = K / 32;
    LOADS(0);
    STORE(0);
    __syncthreads();
#pragma unroll 1
    for (int c = 0; c < NCHUNK; c++) {
        const bool more = (c + 1 < NCHUNK);
        if (more) LOADS(c + 1);   // LDG latency hidden behind the MMAs below
        MMA(c & 1);
        if (more) STORE((c + 1) & 1);
        __syncthreads();
    }

    // ---- epilogue: bias (+ exact-erf GELU), registers -> global ----
    const int gid = lane >> 2;
    const int tig = lane & 3;
    const float* bt = bias + (size_t)t * NFULL + n0;
    float* outT = Out + (size_t)t * OTS + n0;
#pragma unroll
    for (int mf = 0; mf < 2; mf++) {
#pragma unroll
        for (int np = 0; np < 2; np++) {
#pragma unroll
            for (int atom = 0; atom < 2; atom++) {
                const float* a = acc + ((mf * 2 + np) * 2 + atom) * 4;
                int n = nwarp + np * 16 + atom * 8 + tig * 2;
                float bv0 = bt[n], bv1 = bt[n + 1];
                int m0 = mw + mf * 16 + gid;
                float v00 = a[0] + bv0, v01 = a[1] + bv1;
                float v10 = a[2] + bv0, v11 = a[3] + bv1;
                if (DOGELU) {
                    const float r2 = 0.70710678118654752440f;
                    v00 = 0.5f * v00 * (1.0f + erff(v00 * r2));
                    v01 = 0.5f * v01 * (1.0f + erff(v01 * r2));
                    v10 = 0.5f * v10 * (1.0f + erff(v10 * r2));
                    v11 = 0.5f * v11 * (1.0f + erff(v11 * r2));
                }
                *reinterpret_cast<float2*>(outT + (size_t)m0 * OMS + n) = make_float2(v00, v01);
                *reinterpret_cast<float2*>(outT + (size_t)(m0 + 8) * OMS + n) = make_float2(v10, v11);
            }
        }
    }
}

// ───────────── host launcher ─────────────
extern "C" void kernel_launch(void* const* d_in, const int* in_sizes, int n_in,
                              void* d_out, int out_size)
{
    (void)in_sizes; (void)n_in; (void)out_size;
    const float* x  = (const float*)d_in[0];  // [B, T, D]
    const float* W1 = (const float*)d_in[1];  // [T, D, H]
    const float* b1 = (const float*)d_in[2];  // [T, H]
    const float* W2 = (const float*)d_in[3];  // [T, H, D]
    const float* b2 = (const float*)d_in[4];  // [T, D]
    float* out = (float*)d_out;               // [B, T, D]

    float* h = nullptr;
    cudaGetSymbolAddress((void**)&h, g_h);

    // GEMM1 + GELU:  h[t][m][n] = gelu( sum_d x[m,t,d] * W1[t][d,n] + b1[t,n] )
    auto k1 = ffn_mma<DD, HH, DD, TT * DD, BB * HH, HH, true>;
    cudaFuncSetAttribute(k1, cudaFuncAttributeMaxDynamicSharedMemorySize, SMEM_BYTES);
    k1<<<dim3(HH / 128, TT), NT, SMEM_BYTES>>>(W1, x, b1, h);

    // GEMM2: out[m][t][n] = sum_h h[t][m][h] * W2[t][h,n] + b2[t,n]
    auto k2 = ffn_mma<HH, DD, BB * HH, HH, DD, TT * DD, false>;
    cudaFuncSetAttribute(k2, cudaFuncAttributeMaxDynamicSharedMemorySize, SMEM_BYTES);
    k2<<<dim3(DD / 128, TT), NT, SMEM_BYTES>>>(W2, h, b2, out);
}

// round 6
// speedup vs baseline: 1.7121x; 1.7121x over previous
#include <cuda_runtime.h>
#include <cuda_fp16.h>
#include <cstdint>
#include <math.h>

// Problem shape
#define BB 64
#define TT 128
#define DD 512
#define HH 2048

// Intermediate h = gelu(x@W1+b1), layout [t][m][hidx] (fp32, 64MB)
__device__ float g_h[(size_t)TT * BB * HH];

static constexpr int SA = 40;   // padded SMEM row stride in fp16 (80 B, ldsm conflict-free)
static constexpr int NT = 256;  // 8 warps

// dynamic SMEM stage layout (bytes)
static constexpr int A_HI = 0;            // act  [64 m][32 k] fp16 hi  (5120)
static constexpr int A_LO = 5120;         // act lo                      (5120)
static constexpr int W_HI = 10240;        // wgt  [128 n][32 k] fp16    (10240)
static constexpr int STAGE = 20480;
static constexpr int SMEM_BYTES = 2 * STAGE;  // 40960

// ───────────── helpers ─────────────
__device__ __forceinline__ uint32_t smem_u32(const void* p) {
    uint32_t a;
    asm("{ .reg .u64 t; cvta.to.shared.u64 t, %1; cvt.u32.u64 %0, t; }" : "=r"(a) : "l"(p));
    return a;
}
__device__ __forceinline__ void ldsm_x4(uint32_t* r, uint32_t addr) {
    asm volatile("ldmatrix.sync.aligned.m8n8.x4.shared.b16 {%0,%1,%2,%3}, [%4];"
                 : "=r"(r[0]), "=r"(r[1]), "=r"(r[2]), "=r"(r[3]) : "r"(addr));
}
__device__ __forceinline__ void mma16816(float* c, const uint32_t* a, uint32_t b0, uint32_t b1) {
    asm volatile("mma.sync.aligned.m16n8k16.row.col.f32.f16.f16.f32 "
                 "{%0,%1,%2,%3}, {%4,%5,%6,%7}, {%8,%9}, {%0,%1,%2,%3};"
                 : "+f"(c[0]), "+f"(c[1]), "+f"(c[2]), "+f"(c[3])
                 : "r"(a[0]), "r"(a[1]), "r"(a[2]), "r"(a[3]), "r"(b0), "r"(b1));
}
// split two fp32 into packed fp16 hi-pair and lo-pair (x = low half = smaller k)
__device__ __forceinline__ void split2(float x, float y, uint32_t& hi, uint32_t& lo) {
    __half hx = __float2half_rn(x);
    __half hy = __float2half_rn(y);
    __half lx = __float2half_rn(x - __half2float(hx));
    __half ly = __float2half_rn(y - __half2float(hy));
    hi = ((uint32_t)(*reinterpret_cast<uint16_t*>(&hy)) << 16) | *reinterpret_cast<uint16_t*>(&hx);
    lo = ((uint32_t)(*reinterpret_cast<uint16_t*>(&ly)) << 16) | *reinterpret_cast<uint16_t*>(&lx);
}
// round two fp32 to a packed fp16 pair
__device__ __forceinline__ uint32_t pack_h2(float x, float y) {
    __half2 t = __floats2half2_rn(x, y);
    return *reinterpret_cast<uint32_t*>(&t);
}

// ───────────── FFN GEMM via mma.sync (exact-in-A fp16 split, 2 passes, pipelined) ─────────────
// Per CTA: token t, output block n0..n0+127, full batch m=0..63.
//   Out[t*OTS + m*OMS + n0+n] = act( sum_k Act[m,k] * W[t][k, n0+n] + bias[t, n0+n] )
template <int K, int NFULL, int ATS, int AMS, int OTS, int OMS, bool DOGELU>
__global__ void __launch_bounds__(NT)
ffn_mma(const float* __restrict__ W, const float* __restrict__ Act,
        const float* __restrict__ bias, float* __restrict__ Out)
{
    extern __shared__ char smem[];
    const int t    = blockIdx.y;
    const int n0   = blockIdx.x * 128;
    const int tid  = threadIdx.x;
    const int wid  = tid >> 5;
    const int lane = tid & 31;
    const uint32_t sbase = smem_u32(smem);

    const float* At = Act + (size_t)t * ATS;
    const float* Wt = W + (size_t)t * K * NFULL + n0;

    // warp tile: m32 x n32
    const int mw = (wid >> 2) * 32;
    const int nwarp = (wid & 3) * 32;

    // ldmatrix per-lane byte offsets
    const uint32_t aLaneOff = (uint32_t)(((lane & 15) * SA + (lane >> 4) * 8) * 2);
    const uint32_t bLaneOff = (uint32_t)(((((lane >> 4) << 3) + (lane & 7)) * SA +
                                          (((lane >> 3) & 1) * 8) ) * 2);

    // staging assignments
    const int am0 = tid >> 3;               // act: idx 0..255 -> m, k4
    const int ak0 = (tid & 7) * 4;
    const int am1 = (NT + tid) >> 3;        // idx 256..511
    const int ak1 = ((NT + tid) & 7) * 4;
    const int wn  = tid & 127;              // weights: column n, k-group of 16 rows
    const int wkg = tid >> 7;               // 0/1

    float acc[32];                          // [mf][np][atom][4]
#pragma unroll
    for (int i = 0; i < 32; i++) acc[i] = 0.0f;

    float4 pa0, pa1;
    float pw[16];

    auto LOADS = [&](int c) {
        pa0 = *reinterpret_cast<const float4*>(At + (size_t)am0 * AMS + c * 32 + ak0);
        pa1 = *reinterpret_cast<const float4*>(At + (size_t)am1 * AMS + c * 32 + ak1);
        const float* p = Wt + (size_t)(c * 32 + wkg * 16) * NFULL + wn;
#pragma unroll
        for (int r = 0; r < 16; r++) pw[r] = p[(size_t)r * NFULL];
    };

    auto STORE = [&](int s) {
        char* st = smem + s * STAGE;
        {
            uint32_t h0, l0, h1, l1;
            split2(pa0.x, pa0.y, h0, l0); split2(pa0.z, pa0.w, h1, l1);
            int bo = am0 * (SA * 2) + ak0 * 2;
            *reinterpret_cast<uint2*>(st + A_HI + bo) = make_uint2(h0, h1);
            *reinterpret_cast<uint2*>(st + A_LO + bo) = make_uint2(l0, l1);
            split2(pa1.x, pa1.y, h0, l0); split2(pa1.z, pa1.w, h1, l1);
            bo = am1 * (SA * 2) + ak1 * 2;
            *reinterpret_cast<uint2*>(st + A_HI + bo) = make_uint2(h0, h1);
            *reinterpret_cast<uint2*>(st + A_LO + bo) = make_uint2(l0, l1);
        }
        {
            uint32_t h[8];
#pragma unroll
            for (int r = 0; r < 8; r++) h[r] = pack_h2(pw[2 * r], pw[2 * r + 1]);
            int bo = wn * (SA * 2) + wkg * 32;
            *reinterpret_cast<uint4*>(st + W_HI + bo)      = make_uint4(h[0], h[1], h[2], h[3]);
            *reinterpret_cast<uint4*>(st + W_HI + bo + 16) = make_uint4(h[4], h[5], h[6], h[7]);
        }
    };

    auto MMA = [&](int s) {
        const uint32_t ab = sbase + s * STAGE;
        const uint32_t aHi = ab + A_HI + mw * (SA * 2) + aLaneOff;
        const uint32_t aLo = ab + A_LO + mw * (SA * 2) + aLaneOff;
        const uint32_t bHi = ab + W_HI + nwarp * (SA * 2) + bLaneOff;
#pragma unroll
        for (int ks = 0; ks < 2; ks++) {
            uint32_t ah[2][4], al[2][4];
#pragma unroll
            for (int mf = 0; mf < 2; mf++) {
                ldsm_x4(ah[mf], aHi + mf * (16 * SA * 2) + ks * 32);
                ldsm_x4(al[mf], aLo + mf * (16 * SA * 2) + ks * 32);
            }
#pragma unroll
            for (int np = 0; np < 2; np++) {
                uint32_t bh[4];
                ldsm_x4(bh, bHi + np * (16 * SA * 2) + ks * 32);
#pragma unroll
                for (int mf = 0; mf < 2; mf++) {
                    float* c0 = acc + ((mf * 2 + np) * 2 + 0) * 4;
                    float* c1 = acc + ((mf * 2 + np) * 2 + 1) * 4;
                    mma16816(c0, ah[mf], bh[0], bh[1]);
                    mma16816(c1, ah[mf], bh[2], bh[3]);
                    mma16816(c0, al[mf], bh[0], bh[1]);
                    mma16816(c1, al[mf], bh[2], bh[3]);
                }
            }
        }
    };

    constexpr int NCHUNK = K / 32;
    LOADS(0);
    STORE(0);
    __syncthreads();
#pragma unroll 1
    for (int c = 0; c < NCHUNK; c++) {
        const bool more = (c + 1 < NCHUNK);
        if (more) LOADS(c + 1);   // LDG latency hidden behind the MMAs below
        MMA(c & 1);
        if (more) STORE((c + 1) & 1);
        __syncthreads();
    }

    // ---- epilogue: bias (+ exact-erf GELU), registers -> global ----
    const int gid = lane >> 2;
    const int tig = lane & 3;
    const float* bt = bias + (size_t)t * NFULL + n0;
    float* outT = Out + (size_t)t * OTS + n0;
#pragma unroll
    for (int mf = 0; mf < 2; mf++) {
#pragma unroll
        for (int np = 0; np < 2; np++) {
#pragma unroll
            for (int atom = 0; atom < 2; atom++) {
                const float* a = acc + ((mf * 2 + np) * 2 + atom) * 4;
                int n = nwarp + np * 16 + atom * 8 + tig * 2;
                float bv0 = bt[n], bv1 = bt[n + 1];
                int m0 = mw + mf * 16 + gid;
                float v00 = a[0] + bv0, v01 = a[1] + bv1;
                float v10 = a[2] + bv0, v11 = a[3] + bv1;
                if (DOGELU) {
                    const float r2 = 0.70710678118654752440f;
                    v00 = 0.5f * v00 * (1.0f + erff(v00 * r2));
                    v01 = 0.5f * v01 * (1.0f + erff(v01 * r2));
                    v10 = 0.5f * v10 * (1.0f + erff(v10 * r2));
                    v11 = 0.5f * v11 * (1.0f + erff(v11 * r2));
                }
                *reinterpret_cast<float2*>(outT + (size_t)m0 * OMS + n) = make_float2(v00, v01);
                *reinterpret_cast<float2*>(outT + (size_t)(m0 + 8) * OMS + n) = make_float2(v10, v11);
            }
        }
    }
}

// ───────────── host launcher ─────────────
extern "C" void kernel_launch(void* const* d_in, const int* in_sizes, int n_in,
                              void* d_out, int out_size)
{
    (void)in_sizes; (void)n_in; (void)out_size;
    const float* x  = (const float*)d_in[0];  // [B, T, D]
    const float* W1 = (const float*)d_in[1];  // [T, D, H]
    const float* b1 = (const float*)d_in[2];  // [T, H]
    const float* W2 = (const float*)d_in[3];  // [T, H, D]
    const float* b2 = (const float*)d_in[4];  // [T, D]
    float* out = (float*)d_out;               // [B, T, D]

    float* h = nullptr;
    cudaGetSymbolAddress((void**)&h, g_h);

    // GEMM1 + GELU:  h[t][m][n] = gelu( sum_d x[m,t,d] * W1[t][d,n] + b1[t,n] )
    auto k1 = ffn_mma<DD, HH, DD, TT * DD, BB * HH, HH, true>;
    cudaFuncSetAttribute(k1, cudaFuncAttributeMaxDynamicSharedMemorySize, SMEM_BYTES);
    k1<<<dim3(HH / 128, TT), NT, SMEM_BYTES>>>(W1, x, b1, h);

    // GEMM2: out[m][t][n] = sum_h h[t][m][h] * W2[t][h,n] + b2[t,n]
    auto k2 = ffn_mma<HH, DD, BB * HH, HH, DD, TT * DD, false>;
    cudaFuncSetAttribute(k2, cudaFuncAttributeMaxDynamicSharedMemorySize, SMEM_BYTES);
    k2<<<dim3(DD / 128, TT), NT, SMEM_BYTES>>>(W2, h, b2, out);
}

// round 7
// speedup vs baseline: 1.8114x; 1.0580x over previous
#include <cuda_runtime.h>
#include <cuda_fp16.h>
#include <cstdint>
#include <math.h>

// Problem shape
#define BB 64
#define TT 128
#define DD 512
#define HH 2048

// Intermediate h = gelu(x@W1+b1), fp16, layout [t][m][hidx] (32MB)
__device__ __half g_h[(size_t)TT * BB * HH];

static constexpr int SA = 40;   // padded SMEM row stride in fp16 (80 B, ldsm conflict-free)
static constexpr int NT = 256;  // 8 warps

// ───────────── helpers ─────────────
__device__ __forceinline__ uint32_t smem_u32(const void* p) {
    uint32_t a;
    asm("{ .reg .u64 t; cvta.to.shared.u64 t, %1; cvt.u32.u64 %0, t; }" : "=r"(a) : "l"(p));
    return a;
}
__device__ __forceinline__ void ldsm_x4(uint32_t* r, uint32_t addr) {
    asm volatile("ldmatrix.sync.aligned.m8n8.x4.shared.b16 {%0,%1,%2,%3}, [%4];"
                 : "=r"(r[0]), "=r"(r[1]), "=r"(r[2]), "=r"(r[3]) : "r"(addr));
}
__device__ __forceinline__ void mma16816(float* c, const uint32_t* a, uint32_t b0, uint32_t b1) {
    asm volatile("mma.sync.aligned.m16n8k16.row.col.f32.f16.f16.f32 "
                 "{%0,%1,%2,%3}, {%4,%5,%6,%7}, {%8,%9}, {%0,%1,%2,%3};"
                 : "+f"(c[0]), "+f"(c[1]), "+f"(c[2]), "+f"(c[3])
                 : "r"(a[0]), "r"(a[1]), "r"(a[2]), "r"(a[3]), "r"(b0), "r"(b1));
}
// split two fp32 into packed fp16 hi-pair and lo-pair (x = low half = smaller k)
__device__ __forceinline__ void split2(float x, float y, uint32_t& hi, uint32_t& lo) {
    __half hx = __float2half_rn(x);
    __half hy = __float2half_rn(y);
    __half lx = __float2half_rn(x - __half2float(hx));
    __half ly = __float2half_rn(y - __half2float(hy));
    hi = ((uint32_t)(*reinterpret_cast<uint16_t*>(&hy)) << 16) | *reinterpret_cast<uint16_t*>(&hx);
    lo = ((uint32_t)(*reinterpret_cast<uint16_t*>(&ly)) << 16) | *reinterpret_cast<uint16_t*>(&lx);
}
__device__ __forceinline__ uint32_t pack_h2(float x, float y) {
    __half2 t = __floats2half2_rn(x, y);
    return *reinterpret_cast<uint32_t*>(&t);
}
__device__ __forceinline__ float gelu_exact(float v) {
    return 0.5f * v * (1.0f + erff(v * 0.70710678118654752440f));
}

// ═════════════════ GEMM1: x (fp32, split 2-pass) @ W1 → gelu → h (fp16) ═════════════════
// SMEM stage: A_HI/A_LO act [64 m][32 k] fp16 (5120 each), W [128 n][32 k] fp16 (10240)
static constexpr int G1_A_HI = 0;
static constexpr int G1_A_LO = 5120;
static constexpr int G1_W    = 10240;
static constexpr int G1_STAGE = 20480;
static constexpr int G1_SMEM  = 2 * G1_STAGE;  // 40960

__global__ void __launch_bounds__(NT)
ffn_g1(const float* __restrict__ W, const float* __restrict__ Act,
       const float* __restrict__ bias, __half* __restrict__ Out)
{
    constexpr int K = DD, NFULL = HH;
    constexpr int ATS = DD, AMS = TT * DD;        // x: [m][t][d]
    constexpr int OTS = BB * HH, OMS = HH;        // h: [t][m][n]
    extern __shared__ char smem[];
    const int t = blockIdx.y, n0 = blockIdx.x * 128;
    const int tid = threadIdx.x, wid = tid >> 5, lane = tid & 31;
    const uint32_t sbase = smem_u32(smem);

    const float* At = Act + (size_t)t * ATS;
    const float* Wt = W + (size_t)t * K * NFULL + n0;

    const int mw = (wid >> 2) * 32;
    const int nwarp = (wid & 3) * 32;
    const uint32_t aLaneOff = (uint32_t)(((lane & 15) * SA + (lane >> 4) * 8) * 2);
    const uint32_t bLaneOff = (uint32_t)(((((lane >> 4) << 3) + (lane & 7)) * SA +
                                          (((lane >> 3) & 1) * 8)) * 2);

    const int am0 = tid >> 3, ak0 = (tid & 7) * 4;
    const int am1 = (NT + tid) >> 3, ak1 = ((NT + tid) & 7) * 4;
    const int wn = tid & 127, wkg = tid >> 7;

    float acc[32];
#pragma unroll
    for (int i = 0; i < 32; i++) acc[i] = 0.0f;

    float4 pa0, pa1;
    float pw[16];

    auto LOADS = [&](int c) {
        pa0 = *reinterpret_cast<const float4*>(At + (size_t)am0 * AMS + c * 32 + ak0);
        pa1 = *reinterpret_cast<const float4*>(At + (size_t)am1 * AMS + c * 32 + ak1);
        const float* p = Wt + (size_t)(c * 32 + wkg * 16) * NFULL + wn;
#pragma unroll
        for (int r = 0; r < 16; r++) pw[r] = p[(size_t)r * NFULL];
    };
    auto STORE = [&](int s) {
        char* st = smem + s * G1_STAGE;
        uint32_t h0, l0, h1, l1;
        split2(pa0.x, pa0.y, h0, l0); split2(pa0.z, pa0.w, h1, l1);
        int bo = am0 * (SA * 2) + ak0 * 2;
        *reinterpret_cast<uint2*>(st + G1_A_HI + bo) = make_uint2(h0, h1);
        *reinterpret_cast<uint2*>(st + G1_A_LO + bo) = make_uint2(l0, l1);
        split2(pa1.x, pa1.y, h0, l0); split2(pa1.z, pa1.w, h1, l1);
        bo = am1 * (SA * 2) + ak1 * 2;
        *reinterpret_cast<uint2*>(st + G1_A_HI + bo) = make_uint2(h0, h1);
        *reinterpret_cast<uint2*>(st + G1_A_LO + bo) = make_uint2(l0, l1);
        uint32_t hw[8];
#pragma unroll
        for (int r = 0; r < 8; r++) hw[r] = pack_h2(pw[2 * r], pw[2 * r + 1]);
        bo = wn * (SA * 2) + wkg * 32;
        *reinterpret_cast<uint4*>(st + G1_W + bo)      = make_uint4(hw[0], hw[1], hw[2], hw[3]);
        *reinterpret_cast<uint4*>(st + G1_W + bo + 16) = make_uint4(hw[4], hw[5], hw[6], hw[7]);
    };
    auto MMA = [&](int s) {
        const uint32_t ab = sbase + s * G1_STAGE;
        const uint32_t aHi = ab + G1_A_HI + mw * (SA * 2) + aLaneOff;
        const uint32_t aLo = ab + G1_A_LO + mw * (SA * 2) + aLaneOff;
        const uint32_t bHi = ab + G1_W + nwarp * (SA * 2) + bLaneOff;
#pragma unroll
        for (int ks = 0; ks < 2; ks++) {
            uint32_t ah[2][4], al[2][4];
#pragma unroll
            for (int mf = 0; mf < 2; mf++) {
                ldsm_x4(ah[mf], aHi + mf * (16 * SA * 2) + ks * 32);
                ldsm_x4(al[mf], aLo + mf * (16 * SA * 2) + ks * 32);
            }
#pragma unroll
            for (int np = 0; np < 2; np++) {
                uint32_t bh[4];
                ldsm_x4(bh, bHi + np * (16 * SA * 2) + ks * 32);
#pragma unroll
                for (int mf = 0; mf < 2; mf++) {
                    float* c0 = acc + ((mf * 2 + np) * 2 + 0) * 4;
                    float* c1 = acc + ((mf * 2 + np) * 2 + 1) * 4;
                    mma16816(c0, ah[mf], bh[0], bh[1]);
                    mma16816(c1, ah[mf], bh[2], bh[3]);
                    mma16816(c0, al[mf], bh[0], bh[1]);
                    mma16816(c1, al[mf], bh[2], bh[3]);
                }
            }
        }
    };

    constexpr int NCHUNK = K / 32;
    LOADS(0); STORE(0); __syncthreads();
#pragma unroll 1
    for (int c = 0; c < NCHUNK; c++) {
        const bool more = (c + 1 < NCHUNK);
        if (more) LOADS(c + 1);
        MMA(c & 1);
        if (more) STORE((c + 1) & 1);
        __syncthreads();
    }

    // epilogue: bias + exact GELU → fp16 h
    const int gid = lane >> 2, tig = lane & 3;
    const float* bt = bias + (size_t)t * NFULL + n0;
    __half* outT = Out + (size_t)t * OTS + n0;
#pragma unroll
    for (int mf = 0; mf < 2; mf++)
#pragma unroll
        for (int np = 0; np < 2; np++)
#pragma unroll
            for (int atom = 0; atom < 2; atom++) {
                const float* a = acc + ((mf * 2 + np) * 2 + atom) * 4;
                int n = nwarp + np * 16 + atom * 8 + tig * 2;
                float bv0 = bt[n], bv1 = bt[n + 1];
                int m0 = mw + mf * 16 + gid;
                float v00 = gelu_exact(a[0] + bv0), v01 = gelu_exact(a[1] + bv1);
                float v10 = gelu_exact(a[2] + bv0), v11 = gelu_exact(a[3] + bv1);
                *reinterpret_cast<__half2*>(outT + (size_t)m0 * OMS + n) =
                    __floats2half2_rn(v00, v01);
                *reinterpret_cast<__half2*>(outT + (size_t)(m0 + 8) * OMS + n) =
                    __floats2half2_rn(v10, v11);
            }
}

// ═════════════════ GEMM2: h (fp16, single-pass) @ W2 → out (fp32) ═════════════════
// SMEM stage: A act [64 m][32 k] fp16 (5120), W [128 n][32 k] fp16 (10240)
static constexpr int G2_A = 0;
static constexpr int G2_W = 5120;
static constexpr int G2_STAGE = 15360;
static constexpr int G2_SMEM  = 2 * G2_STAGE;  // 30720

__global__ void __launch_bounds__(NT)
ffn_g2(const float* __restrict__ W, const __half* __restrict__ Act,
       const float* __restrict__ bias, float* __restrict__ Out)
{
    constexpr int K = HH, NFULL = DD;
    constexpr int ATS = BB * HH, AMS = HH;        // h: [t][m][k]
    constexpr int OTS = DD, OMS = TT * DD;        // out: [m][t][n]
    extern __shared__ char smem[];
    const int t = blockIdx.y, n0 = blockIdx.x * 128;
    const int tid = threadIdx.x, wid = tid >> 5, lane = tid & 31;
    const uint32_t sbase = smem_u32(smem);

    const __half* At = Act + (size_t)t * ATS;
    const float* Wt = W + (size_t)t * K * NFULL + n0;

    const int mw = (wid >> 2) * 32;
    const int nwarp = (wid & 3) * 32;
    const uint32_t aLaneOff = (uint32_t)(((lane & 15) * SA + (lane >> 4) * 8) * 2);
    const uint32_t bLaneOff = (uint32_t)(((((lane >> 4) << 3) + (lane & 7)) * SA +
                                          (((lane >> 3) & 1) * 8)) * 2);

    // act staging: 64 rows × 32 halves; thread -> (m = tid>>2, 8-half group = tid&3)
    const int am = tid >> 2, ak8 = (tid & 3) * 8;
    const int wn = tid & 127, wkg = tid >> 7;

    float acc[32];
#pragma unroll
    for (int i = 0; i < 32; i++) acc[i] = 0.0f;

    uint4 pa;
    float pw[16];

    auto LOADS = [&](int c) {
        pa = *reinterpret_cast<const uint4*>(At + (size_t)am * AMS + c * 32 + ak8);
        const float* p = Wt + (size_t)(c * 32 + wkg * 16) * NFULL + wn;
#pragma unroll
        for (int r = 0; r < 16; r++) pw[r] = p[(size_t)r * NFULL];
    };
    auto STORE = [&](int s) {
        char* st = smem + s * G2_STAGE;
        *reinterpret_cast<uint4*>(st + G2_A + am * (SA * 2) + ak8 * 2) = pa;
        uint32_t hw[8];
#pragma unroll
        for (int r = 0; r < 8; r++) hw[r] = pack_h2(pw[2 * r], pw[2 * r + 1]);
        int bo = wn * (SA * 2) + wkg * 32;
        *reinterpret_cast<uint4*>(st + G2_W + bo)      = make_uint4(hw[0], hw[1], hw[2], hw[3]);
        *reinterpret_cast<uint4*>(st + G2_W + bo + 16) = make_uint4(hw[4], hw[5], hw[6], hw[7]);
    };
    auto MMA = [&](int s) {
        const uint32_t ab = sbase + s * G2_STAGE;
        const uint32_t aB = ab + G2_A + mw * (SA * 2) + aLaneOff;
        const uint32_t bB = ab + G2_W + nwarp * (SA * 2) + bLaneOff;
#pragma unroll
        for (int ks = 0; ks < 2; ks++) {
            uint32_t ah[2][4];
#pragma unroll
            for (int mf = 0; mf < 2; mf++)
                ldsm_x4(ah[mf], aB + mf * (16 * SA * 2) + ks * 32);
#pragma unroll
            for (int np = 0; np < 2; np++) {
                uint32_t bh[4];
                ldsm_x4(bh, bB + np * (16 * SA * 2) + ks * 32);
#pragma unroll
                for (int mf = 0; mf < 2; mf++) {
                    float* c0 = acc + ((mf * 2 + np) * 2 + 0) * 4;
                    float* c1 = acc + ((mf * 2 + np) * 2 + 1) * 4;
                    mma16816(c0, ah[mf], bh[0], bh[1]);
                    mma16816(c1, ah[mf], bh[2], bh[3]);
                }
            }
        }
    };

    constexpr int NCHUNK = K / 32;
    LOADS(0); STORE(0); __syncthreads();
#pragma unroll 1
    for (int c = 0; c < NCHUNK; c++) {
        const bool more = (c + 1 < NCHUNK);
        if (more) LOADS(c + 1);
        MMA(c & 1);
        if (more) STORE((c + 1) & 1);
        __syncthreads();
    }

    // epilogue: bias, fp32 out
    const int gid = lane >> 2, tig = lane & 3;
    const float* bt = bias + (size_t)t * NFULL + n0;
    float* outT = Out + (size_t)t * OTS + n0;
#pragma unroll
    for (int mf = 0; mf < 2; mf++)
#pragma unroll
        for (int np = 0; np < 2; np++)
#pragma unroll
            for (int atom = 0; atom < 2; atom++) {
                const float* a = acc + ((mf * 2 + np) * 2 + atom) * 4;
                int n = nwarp + np * 16 + atom * 8 + tig * 2;
                float bv0 = bt[n], bv1 = bt[n + 1];
                int m0 = mw + mf * 16 + gid;
                *reinterpret_cast<float2*>(outT + (size_t)m0 * OMS + n) =
                    make_float2(a[0] + bv0, a[1] + bv1);
                *reinterpret_cast<float2*>(outT + (size_t)(m0 + 8) * OMS + n) =
                    make_float2(a[2] + bv0, a[3] + bv1);
            }
}

// ───────────── host launcher ─────────────
extern "C" void kernel_launch(void* const* d_in, const int* in_sizes, int n_in,
                              void* d_out, int out_size)
{
    (void)in_sizes; (void)n_in; (void)out_size;
    const float* x  = (const float*)d_in[0];  // [B, T, D]
    const float* W1 = (const float*)d_in[1];  // [T, D, H]
    const float* b1 = (const float*)d_in[2];  // [T, H]
    const float* W2 = (const float*)d_in[3];  // [T, H, D]
    const float* b2 = (const float*)d_in[4];  // [T, D]
    float* out = (float*)d_out;               // [B, T, D]

    __half* h = nullptr;
    cudaGetSymbolAddress((void**)&h, g_h);

    cudaFuncSetAttribute(ffn_g1, cudaFuncAttributeMaxDynamicSharedMemorySize, G1_SMEM);
    ffn_g1<<<dim3(HH / 128, TT), NT, G1_SMEM>>>(W1, x, b1, h);

    cudaFuncSetAttribute(ffn_g2, cudaFuncAttributeMaxDynamicSharedMemorySize, G2_SMEM);
    ffn_g2<<<dim3(DD / 128, TT), NT, G2_SMEM>>>(W2, h, b2, out);
}

// round 8
// speedup vs baseline: 1.9659x; 1.0853x over previous
#include <cuda_runtime.h>
#include <cuda_fp16.h>
#include <cstdint>
#include <math.h>

// Problem shape
#define BB 64
#define TT 128
#define DD 512
#define HH 2048

// h = gelu(x@W1+b1), fp16, layout [t][m][hidx] (32MB)
__device__ __half g_h[(size_t)TT * BB * HH];
// split-K partial sums for GEMM2: [kv][m][t][n] fp32 (64MB)
static constexpr int NKV = 4;
__device__ float g_part[(size_t)NKV * BB * TT * DD];

static constexpr int SA = 40;   // padded SMEM row stride in fp16 (80 B, ldsm conflict-free)
static constexpr int NT = 256;  // 8 warps

// SMEM stage (both GEMMs): A [64 m][32 k] fp16 (5120), W [128 n][32 k] fp16 (10240)
static constexpr int S_A = 0;
static constexpr int S_W = 5120;
static constexpr int STAGE = 15360;
static constexpr int SMEM_BYTES = 2 * STAGE;  // 30720

// ───────────── helpers ─────────────
__device__ __forceinline__ uint32_t smem_u32(const void* p) {
    uint32_t a;
    asm("{ .reg .u64 t; cvta.to.shared.u64 t, %1; cvt.u32.u64 %0, t; }" : "=r"(a) : "l"(p));
    return a;
}
__device__ __forceinline__ void ldsm_x4(uint32_t* r, uint32_t addr) {
    asm volatile("ldmatrix.sync.aligned.m8n8.x4.shared.b16 {%0,%1,%2,%3}, [%4];"
                 : "=r"(r[0]), "=r"(r[1]), "=r"(r[2]), "=r"(r[3]) : "r"(addr));
}
__device__ __forceinline__ void mma16816(float* c, const uint32_t* a, uint32_t b0, uint32_t b1) {
    asm volatile("mma.sync.aligned.m16n8k16.row.col.f32.f16.f16.f32 "
                 "{%0,%1,%2,%3}, {%4,%5,%6,%7}, {%8,%9}, {%0,%1,%2,%3};"
                 : "+f"(c[0]), "+f"(c[1]), "+f"(c[2]), "+f"(c[3])
                 : "r"(a[0]), "r"(a[1]), "r"(a[2]), "r"(a[3]), "r"(b0), "r"(b1));
}
__device__ __forceinline__ uint32_t pack_h2(float x, float y) {
    __half2 t = __floats2half2_rn(x, y);
    return *reinterpret_cast<uint32_t*>(&t);
}
__device__ __forceinline__ float gelu_exact(float v) {
    return 0.5f * v * (1.0f + erff(v * 0.70710678118654752440f));
}

// ═════════════ GEMM1: x (fp32→fp16 single pass) @ W1 → gelu → h (fp16) ═════════════
__global__ void __launch_bounds__(NT)
ffn_g1(const float* __restrict__ W, const float* __restrict__ Act,
       const float* __restrict__ bias, __half* __restrict__ Out)
{
    constexpr int K = DD, NFULL = HH;
    constexpr int ATS = DD, AMS = TT * DD;        // x: [m][t][d]
    constexpr int OTS = BB * HH, OMS = HH;        // h: [t][m][n]
    extern __shared__ char smem[];
    const int t = blockIdx.y, n0 = blockIdx.x * 128;
    const int tid = threadIdx.x, wid = tid >> 5, lane = tid & 31;
    const uint32_t sbase = smem_u32(smem);

    const float* At = Act + (size_t)t * ATS;
    const float* Wt = W + (size_t)t * K * NFULL + n0;

    const int mw = (wid >> 2) * 32;
    const int nwarp = (wid & 3) * 32;
    const uint32_t aLaneOff = (uint32_t)(((lane & 15) * SA + (lane >> 4) * 8) * 2);
    const uint32_t bLaneOff = (uint32_t)(((((lane >> 4) << 3) + (lane & 7)) * SA +
                                          (((lane >> 3) & 1) * 8)) * 2);

    const int am = tid >> 2, ak8 = (tid & 3) * 8;  // 64 rows x 8 consecutive k
    const int wn = tid & 127, wkg = tid >> 7;

    float acc[32];
#pragma unroll
    for (int i = 0; i < 32; i++) acc[i] = 0.0f;

    float4 pa0, pa1;
    float pw[16];

    auto LOADS = [&](int c) {
        const float* ap = At + (size_t)am * AMS + c * 32 + ak8;
        pa0 = *reinterpret_cast<const float4*>(ap);
        pa1 = *reinterpret_cast<const float4*>(ap + 4);
        const float* p = Wt + (size_t)(c * 32 + wkg * 16) * NFULL + wn;
#pragma unroll
        for (int r = 0; r < 16; r++) pw[r] = p[(size_t)r * NFULL];
    };
    auto STORE = [&](int s) {
        char* st = smem + s * STAGE;
        uint4 av = make_uint4(pack_h2(pa0.x, pa0.y), pack_h2(pa0.z, pa0.w),
                              pack_h2(pa1.x, pa1.y), pack_h2(pa1.z, pa1.w));
        *reinterpret_cast<uint4*>(st + S_A + am * (SA * 2) + ak8 * 2) = av;
        uint32_t hw[8];
#pragma unroll
        for (int r = 0; r < 8; r++) hw[r] = pack_h2(pw[2 * r], pw[2 * r + 1]);
        int bo = wn * (SA * 2) + wkg * 32;
        *reinterpret_cast<uint4*>(st + S_W + bo)      = make_uint4(hw[0], hw[1], hw[2], hw[3]);
        *reinterpret_cast<uint4*>(st + S_W + bo + 16) = make_uint4(hw[4], hw[5], hw[6], hw[7]);
    };
    auto MMA = [&](int s) {
        const uint32_t ab = sbase + s * STAGE;
        const uint32_t aB = ab + S_A + mw * (SA * 2) + aLaneOff;
        const uint32_t bB = ab + S_W + nwarp * (SA * 2) + bLaneOff;
#pragma unroll
        for (int ks = 0; ks < 2; ks++) {
            uint32_t ah[2][4];
#pragma unroll
            for (int mf = 0; mf < 2; mf++)
                ldsm_x4(ah[mf], aB + mf * (16 * SA * 2) + ks * 32);
#pragma unroll
            for (int np = 0; np < 2; np++) {
                uint32_t bh[4];
                ldsm_x4(bh, bB + np * (16 * SA * 2) + ks * 32);
#pragma unroll
                for (int mf = 0; mf < 2; mf++) {
                    float* c0 = acc + ((mf * 2 + np) * 2 + 0) * 4;
                    float* c1 = acc + ((mf * 2 + np) * 2 + 1) * 4;
                    mma16816(c0, ah[mf], bh[0], bh[1]);
                    mma16816(c1, ah[mf], bh[2], bh[3]);
                }
            }
        }
    };

    constexpr int NCHUNK = K / 32;
    LOADS(0); STORE(0); __syncthreads();
#pragma unroll 1
    for (int c = 0; c < NCHUNK; c++) {
        const bool more = (c + 1 < NCHUNK);
        if (more) LOADS(c + 1);
        MMA(c & 1);
        if (more) STORE((c + 1) & 1);
        __syncthreads();
    }

    // epilogue: bias + exact GELU → fp16 h
    const int gid = lane >> 2, tig = lane & 3;
    const float* bt = bias + (size_t)t * NFULL + n0;
    __half* outT = Out + (size_t)t * OTS + n0;
#pragma unroll
    for (int mf = 0; mf < 2; mf++)
#pragma unroll
        for (int np = 0; np < 2; np++)
#pragma unroll
            for (int atom = 0; atom < 2; atom++) {
                const float* a = acc + ((mf * 2 + np) * 2 + atom) * 4;
                int n = nwarp + np * 16 + atom * 8 + tig * 2;
                float bv0 = bt[n], bv1 = bt[n + 1];
                int m0 = mw + mf * 16 + gid;
                *reinterpret_cast<__half2*>(outT + (size_t)m0 * OMS + n) =
                    __floats2half2_rn(gelu_exact(a[0] + bv0), gelu_exact(a[1] + bv1));
                *reinterpret_cast<__half2*>(outT + (size_t)(m0 + 8) * OMS + n) =
                    __floats2half2_rn(gelu_exact(a[2] + bv0), gelu_exact(a[3] + bv1));
            }
}

// ═════════════ GEMM2: h (fp16) @ W2, split-K=4 → fp32 partials ═════════════
__global__ void __launch_bounds__(NT)
ffn_g2(const float* __restrict__ W, const __half* __restrict__ Act,
       float* __restrict__ Part)
{
    constexpr int K = HH, NFULL = DD;
    constexpr int ATS = BB * HH, AMS = HH;        // h: [t][m][k]
    constexpr int OTS = DD, OMS = TT * DD;        // partial: [kv][m][t][n]
    constexpr int NCHUNK_TOT = K / 32;            // 64
    constexpr int CPK = NCHUNK_TOT / NKV;         // 16 chunks per K-piece
    extern __shared__ char smem[];
    const int t = blockIdx.y, n0 = blockIdx.x * 128;
    const int kv = blockIdx.z;
    const int tid = threadIdx.x, wid = tid >> 5, lane = tid & 31;
    const uint32_t sbase = smem_u32(smem);

    const __half* At = Act + (size_t)t * ATS + kv * (CPK * 32);
    const float* Wt = W + (size_t)t * K * NFULL + (size_t)(kv * CPK * 32) * NFULL + n0;

    const int mw = (wid >> 2) * 32;
    const int nwarp = (wid & 3) * 32;
    const uint32_t aLaneOff = (uint32_t)(((lane & 15) * SA + (lane >> 4) * 8) * 2);
    const uint32_t bLaneOff = (uint32_t)(((((lane >> 4) << 3) + (lane & 7)) * SA +
                                          (((lane >> 3) & 1) * 8)) * 2);

    const int am = tid >> 2, ak8 = (tid & 3) * 8;
    const int wn = tid & 127, wkg = tid >> 7;

    float acc[32];
#pragma unroll
    for (int i = 0; i < 32; i++) acc[i] = 0.0f;

    uint4 pa;
    float pw[16];

    auto LOADS = [&](int c) {
        pa = *reinterpret_cast<const uint4*>(At + (size_t)am * AMS + c * 32 + ak8);
        const float* p = Wt + (size_t)(c * 32 + wkg * 16) * NFULL + wn;
#pragma unroll
        for (int r = 0; r < 16; r++) pw[r] = p[(size_t)r * NFULL];
    };
    auto STORE = [&](int s) {
        char* st = smem + s * STAGE;
        *reinterpret_cast<uint4*>(st + S_A + am * (SA * 2) + ak8 * 2) = pa;
        uint32_t hw[8];
#pragma unroll
        for (int r = 0; r < 8; r++) hw[r] = pack_h2(pw[2 * r], pw[2 * r + 1]);
        int bo = wn * (SA * 2) + wkg * 32;
        *reinterpret_cast<uint4*>(st + S_W + bo)      = make_uint4(hw[0], hw[1], hw[2], hw[3]);
        *reinterpret_cast<uint4*>(st + S_W + bo + 16) = make_uint4(hw[4], hw[5], hw[6], hw[7]);
    };
    auto MMA = [&](int s) {
        const uint32_t ab = sbase + s * STAGE;
        const uint32_t aB = ab + S_A + mw * (SA * 2) + aLaneOff;
        const uint32_t bB = ab + S_W + nwarp * (SA * 2) + bLaneOff;
#pragma unroll
        for (int ks = 0; ks < 2; ks++) {
            uint32_t ah[2][4];
#pragma unroll
            for (int mf = 0; mf < 2; mf++)
                ldsm_x4(ah[mf], aB + mf * (16 * SA * 2) + ks * 32);
#pragma unroll
            for (int np = 0; np < 2; np++) {
                uint32_t bh[4];
                ldsm_x4(bh, bB + np * (16 * SA * 2) + ks * 32);
#pragma unroll
                for (int mf = 0; mf < 2; mf++) {
                    float* c0 = acc + ((mf * 2 + np) * 2 + 0) * 4;
                    float* c1 = acc + ((mf * 2 + np) * 2 + 1) * 4;
                    mma16816(c0, ah[mf], bh[0], bh[1]);
                    mma16816(c1, ah[mf], bh[2], bh[3]);
                }
            }
        }
    };

    LOADS(0); STORE(0); __syncthreads();
#pragma unroll 1
    for (int c = 0; c < CPK; c++) {
        const bool more = (c + 1 < CPK);
        if (more) LOADS(c + 1);
        MMA(c & 1);
        if (more) STORE((c + 1) & 1);
        __syncthreads();
    }

    // epilogue: raw partial sums (bias added in reduce)
    const int gid = lane >> 2, tig = lane & 3;
    float* outT = Part + (size_t)kv * (BB * TT * DD) + (size_t)t * OTS + n0;
#pragma unroll
    for (int mf = 0; mf < 2; mf++)
#pragma unroll
        for (int np = 0; np < 2; np++)
#pragma unroll
            for (int atom = 0; atom < 2; atom++) {
                const float* a = acc + ((mf * 2 + np) * 2 + atom) * 4;
                int n = nwarp + np * 16 + atom * 8 + tig * 2;
                int m0 = mw + mf * 16 + gid;
                *reinterpret_cast<float2*>(outT + (size_t)m0 * OMS + n) =
                    make_float2(a[0], a[1]);
                *reinterpret_cast<float2*>(outT + (size_t)(m0 + 8) * OMS + n) =
                    make_float2(a[2], a[3]);
            }
}

// ═════════════ reduce: out = sum_kv part[kv] + bias ═════════════
__global__ void __launch_bounds__(256)
ffn_reduce(const float* __restrict__ Part, const float* __restrict__ bias,
           float* __restrict__ Out)
{
    constexpr size_t NQ = (size_t)BB * TT * DD / 4;       // float4 count = 2^21
    constexpr uint32_t BMASK = (TT * DD / 4) - 1;          // bias float4 index mask (2^14-1)
    size_t i = (size_t)blockIdx.x * 256 + threadIdx.x;
    const float4* p = reinterpret_cast<const float4*>(Part);
    float4 a = p[i];
    float4 b = p[i + NQ];
    float4 c = p[i + 2 * NQ];
    float4 d = p[i + 3 * NQ];
    float4 bv = reinterpret_cast<const float4*>(bias)[(uint32_t)i & BMASK];
    float4 o;
    o.x = a.x + b.x + c.x + d.x + bv.x;
    o.y = a.y + b.y + c.y + d.y + bv.y;
    o.z = a.z + b.z + c.z + d.z + bv.z;
    o.w = a.w + b.w + c.w + d.w + bv.w;
    reinterpret_cast<float4*>(Out)[i] = o;
}

// ───────────── host launcher ─────────────
extern "C" void kernel_launch(void* const* d_in, const int* in_sizes, int n_in,
                              void* d_out, int out_size)
{
    (void)in_sizes; (void)n_in; (void)out_size;
    const float* x  = (const float*)d_in[0];  // [B, T, D]
    const float* W1 = (const float*)d_in[1];  // [T, D, H]
    const float* b1 = (const float*)d_in[2];  // [T, H]
    const float* W2 = (const float*)d_in[3];  // [T, H, D]
    const float* b2 = (const float*)d_in[4];  // [T, D]
    float* out = (float*)d_out;               // [B, T, D]

    __half* h = nullptr;
    cudaGetSymbolAddress((void**)&h, g_h);
    float* part = nullptr;
    cudaGetSymbolAddress((void**)&part, g_part);

    cudaFuncSetAttribute(ffn_g1, cudaFuncAttributeMaxDynamicSharedMemorySize, SMEM_BYTES);
    ffn_g1<<<dim3(HH / 128, TT), NT, SMEM_BYTES>>>(W1, x, b1, h);

    cudaFuncSetAttribute(ffn_g2, cudaFuncAttributeMaxDynamicSharedMemorySize, SMEM_BYTES);
    ffn_g2<<<dim3(DD / 128, TT, NKV), NT, SMEM_BYTES>>>(W2, h, part);

    ffn_reduce<<<(BB * TT * DD / 4) / 256, 256>>>(part, b2, out);
}

// round 9
// speedup vs baseline: 2.2129x; 1.1257x over previous
#include <cuda_runtime.h>
#include <cuda_fp16.h>
#include <cstdint>
#include <math.h>

// Problem shape
#define BB 64
#define TT 128
#define DD 512
#define HH 2048

// h = gelu(x@W1+b1), fp16, layout [t][m][hidx] (32MB)
__device__ __half g_h[(size_t)TT * BB * HH];
// split-K partial sums for GEMM2: [kv][m][t][n] fp32
static constexpr int NKV = 4;
__device__ float g_part[(size_t)NKV * BB * TT * DD];

static constexpr int SA = 40;   // padded SMEM row stride in fp16 (80 B, ldsm conflict-free)
static constexpr int NT = 256;  // 8 warps

// SMEM layout (bytes): two mma stages + two raw fp32 weight stages
static constexpr int S_A   = 0;      // act  [64 m][32 k] fp16 (5120)
static constexpr int S_W   = 5120;   // wgt  [128 n][32 k] fp16 (10240)
static constexpr int STAGE = 15360;
static constexpr int RAW0  = 2 * STAGE;   // 30720
static constexpr int RAWSZ = 16384;       // 32 k-rows x 128 n-cols fp32
static constexpr int SMEM_BYTES = RAW0 + 2 * RAWSZ;  // 63488

// ───────────── helpers ─────────────
__device__ __forceinline__ uint32_t smem_u32(const void* p) {
    uint32_t a;
    asm("{ .reg .u64 t; cvta.to.shared.u64 t, %1; cvt.u32.u64 %0, t; }" : "=r"(a) : "l"(p));
    return a;
}
#define CP_ASYNC16(dst, src) \
    asm volatile("cp.async.cg.shared.global [%0], [%1], 16;" :: "r"(dst), "l"(src) : "memory")
#define CP_COMMIT() asm volatile("cp.async.commit_group;" ::: "memory")
#define CP_WAIT1()  asm volatile("cp.async.wait_group 1;" ::: "memory")

__device__ __forceinline__ void ldsm_x4(uint32_t* r, uint32_t addr) {
    asm volatile("ldmatrix.sync.aligned.m8n8.x4.shared.b16 {%0,%1,%2,%3}, [%4];"
                 : "=r"(r[0]), "=r"(r[1]), "=r"(r[2]), "=r"(r[3]) : "r"(addr));
}
__device__ __forceinline__ void mma16816(float* c, const uint32_t* a, uint32_t b0, uint32_t b1) {
    asm volatile("mma.sync.aligned.m16n8k16.row.col.f32.f16.f16.f32 "
                 "{%0,%1,%2,%3}, {%4,%5,%6,%7}, {%8,%9}, {%0,%1,%2,%3};"
                 : "+f"(c[0]), "+f"(c[1]), "+f"(c[2]), "+f"(c[3])
                 : "r"(a[0]), "r"(a[1]), "r"(a[2]), "r"(a[3]), "r"(b0), "r"(b1));
}
__device__ __forceinline__ uint32_t pack_h2(float x, float y) {
    __half2 t = __floats2half2_rn(x, y);
    return *reinterpret_cast<uint32_t*>(&t);
}
__device__ __forceinline__ float gelu_exact(float v) {
    return 0.5f * v * (1.0f + erff(v * 0.70710678118654752440f));
}

// ═════════════ GEMM1: x (fp32→fp16) @ W1 → gelu → h (fp16) ═════════════
__global__ void __launch_bounds__(NT)
ffn_g1(const float* __restrict__ W, const float* __restrict__ Act,
       const float* __restrict__ bias, __half* __restrict__ Out)
{
    constexpr int K = DD, NFULL = HH;
    constexpr int ATS = DD, AMS = TT * DD;        // x: [m][t][d]
    constexpr int OTS = BB * HH, OMS = HH;        // h: [t][m][n]
    extern __shared__ char smem[];
    const int t = blockIdx.y, n0 = blockIdx.x * 128;
    const int tid = threadIdx.x, wid = tid >> 5, lane = tid & 31;
    const uint32_t sbase = smem_u32(smem);

    const float* At = Act + (size_t)t * ATS;
    const float* Wt = W + (size_t)t * K * NFULL + n0;

    const int mw = (wid >> 2) * 32;
    const int nwarp = (wid & 3) * 32;
    const uint32_t aLaneOff = (uint32_t)(((lane & 15) * SA + (lane >> 4) * 8) * 2);
    const uint32_t bLaneOff = (uint32_t)(((((lane >> 4) << 3) + (lane & 7)) * SA +
                                          (((lane >> 3) & 1) * 8)) * 2);

    const int am = tid >> 2, ak8 = (tid & 3) * 8;  // act: 64 rows x 8 consecutive k
    const int wn = tid & 127, wkg = tid >> 7;      // convert: column, 16-row group

    float acc[32];
#pragma unroll
    for (int i = 0; i < 32; i++) acc[i] = 0.0f;

    float4 pa0, pa1;

    // cp.async a full 32x128 fp32 W tile into raw stage s (4x16B per thread)
    auto WASYNC = [&](int c, int s) {
        const float* base = Wt + (size_t)(c * 32) * NFULL;
        uint32_t dst = sbase + RAW0 + s * RAWSZ + tid * 16;
#pragma unroll
        for (int j = 0; j < 4; j++) {
            int o = tid + 256 * j;
            const float* src = base + (size_t)(o >> 5) * NFULL + (o & 31) * 4;
            CP_ASYNC16(dst + j * 4096, src);
        }
    };
    auto LOADX = [&](int c) {
        const float* ap = At + (size_t)am * AMS + c * 32 + ak8;
        pa0 = *reinterpret_cast<const float4*>(ap);
        pa1 = *reinterpret_cast<const float4*>(ap + 4);
    };
    auto STOREX = [&](int s) {
        char* st = smem + s * STAGE;
        uint4 av = make_uint4(pack_h2(pa0.x, pa0.y), pack_h2(pa0.z, pa0.w),
                              pack_h2(pa1.x, pa1.y), pack_h2(pa1.z, pa1.w));
        *reinterpret_cast<uint4*>(st + S_A + am * (SA * 2) + ak8 * 2) = av;
    };
    // convert raw fp32 stage -> padded fp16 W region [128 n][32 k]
    auto CONVW = [&](int s) {
        const float* raw = reinterpret_cast<const float*>(smem + RAW0 + s * RAWSZ);
        char* st = smem + s * STAGE;
        float pw[16];
#pragma unroll
        for (int r = 0; r < 16; r++) pw[r] = raw[(wkg * 16 + r) * 128 + wn];
        uint32_t hw[8];
#pragma unroll
        for (int r = 0; r < 8; r++) hw[r] = pack_h2(pw[2 * r], pw[2 * r + 1]);
        int bo = wn * (SA * 2) + wkg * 32;
        *reinterpret_cast<uint4*>(st + S_W + bo)      = make_uint4(hw[0], hw[1], hw[2], hw[3]);
        *reinterpret_cast<uint4*>(st + S_W + bo + 16) = make_uint4(hw[4], hw[5], hw[6], hw[7]);
    };
    auto MMA = [&](int s) {
        const uint32_t ab = sbase + s * STAGE;
        const uint32_t aB = ab + S_A + mw * (SA * 2) + aLaneOff;
        const uint32_t bB = ab + S_W + nwarp * (SA * 2) + bLaneOff;
#pragma unroll
        for (int ks = 0; ks < 2; ks++) {
            uint32_t ah[2][4];
#pragma unroll
            for (int mf = 0; mf < 2; mf++)
                ldsm_x4(ah[mf], aB + mf * (16 * SA * 2) + ks * 32);
#pragma unroll
            for (int np = 0; np < 2; np++) {
                uint32_t bh[4];
                ldsm_x4(bh, bB + np * (16 * SA * 2) + ks * 32);
#pragma unroll
                for (int mf = 0; mf < 2; mf++) {
                    float* c0 = acc + ((mf * 2 + np) * 2 + 0) * 4;
                    float* c1 = acc + ((mf * 2 + np) * 2 + 1) * 4;
                    mma16816(c0, ah[mf], bh[0], bh[1]);
                    mma16816(c1, ah[mf], bh[2], bh[3]);
                }
            }
        }
    };

    constexpr int NCHUNK = K / 32;
    WASYNC(0, 0); CP_COMMIT();
    WASYNC(1, 1); CP_COMMIT();
    LOADX(0);
    CP_WAIT1(); __syncthreads();
    STOREX(0); CONVW(0);
    __syncthreads();
#pragma unroll 1
    for (int c = 0; c < NCHUNK; c++) {
        if (c + 1 < NCHUNK) LOADX(c + 1);
        if (c + 2 < NCHUNK) WASYNC(c + 2, (c + 2) & 1);
        CP_COMMIT();
        MMA(c & 1);
        CP_WAIT1();
        __syncthreads();
        if (c + 1 < NCHUNK) { STOREX((c + 1) & 1); CONVW((c + 1) & 1); }
        __syncthreads();
    }

    // epilogue: bias + exact GELU → fp16 h
    const int gid = lane >> 2, tig = lane & 3;
    const float* bt = bias + (size_t)t * NFULL + n0;
    __half* outT = Out + (size_t)t * OTS + n0;
#pragma unroll
    for (int mf = 0; mf < 2; mf++)
#pragma unroll
        for (int np = 0; np < 2; np++)
#pragma unroll
            for (int atom = 0; atom < 2; atom++) {
                const float* a = acc + ((mf * 2 + np) * 2 + atom) * 4;
                int n = nwarp + np * 16 + atom * 8 + tig * 2;
                float bv0 = bt[n], bv1 = bt[n + 1];
                int m0 = mw + mf * 16 + gid;
                *reinterpret_cast<__half2*>(outT + (size_t)m0 * OMS + n) =
                    __floats2half2_rn(gelu_exact(a[0] + bv0), gelu_exact(a[1] + bv1));
                *reinterpret_cast<__half2*>(outT + (size_t)(m0 + 8) * OMS + n) =
                    __floats2half2_rn(gelu_exact(a[2] + bv0), gelu_exact(a[3] + bv1));
            }
}

// ═════════════ GEMM2: h (fp16, cp.async) @ W2, split-K=4 → fp32 partials ═════════════
__global__ void __launch_bounds__(NT)
ffn_g2(const float* __restrict__ W, const __half* __restrict__ Act,
       float* __restrict__ Part)
{
    constexpr int K = HH, NFULL = DD;
    constexpr int ATS = BB * HH, AMS = HH;        // h: [t][m][k]
    constexpr int OTS = DD, OMS = TT * DD;        // partial: [kv][m][t][n]
    constexpr int CPK = (K / 32) / NKV;           // 16 chunks per K-piece
    extern __shared__ char smem[];
    const int t = blockIdx.y, n0 = blockIdx.x * 128;
    const int kv = blockIdx.z;
    const int tid = threadIdx.x, wid = tid >> 5, lane = tid & 31;
    const uint32_t sbase = smem_u32(smem);

    const __half* At = Act + (size_t)t * ATS + kv * (CPK * 32);
    const float* Wt = W + (size_t)t * K * NFULL + (size_t)(kv * CPK * 32) * NFULL + n0;

    const int mw = (wid >> 2) * 32;
    const int nwarp = (wid & 3) * 32;
    const uint32_t aLaneOff = (uint32_t)(((lane & 15) * SA + (lane >> 4) * 8) * 2);
    const uint32_t bLaneOff = (uint32_t)(((((lane >> 4) << 3) + (lane & 7)) * SA +
                                          (((lane >> 3) & 1) * 8)) * 2);

    const int am = tid >> 2, ak8 = (tid & 3) * 8;
    const int wn = tid & 127, wkg = tid >> 7;

    float acc[32];
#pragma unroll
    for (int i = 0; i < 32; i++) acc[i] = 0.0f;

    auto WASYNC = [&](int c, int s) {
        const float* base = Wt + (size_t)(c * 32) * NFULL;
        uint32_t dst = sbase + RAW0 + s * RAWSZ + tid * 16;
#pragma unroll
        for (int j = 0; j < 4; j++) {
            int o = tid + 256 * j;
            const float* src = base + (size_t)(o >> 5) * NFULL + (o & 31) * 4;
            CP_ASYNC16(dst + j * 4096, src);
        }
    };
    // act is fp16 in gmem: cp.async straight into the ldsm-ready A region
    auto AACT = [&](int c, int s) {
        uint32_t dst = sbase + s * STAGE + S_A + am * (SA * 2) + ak8 * 2;
        const __half* src = At + (size_t)am * AMS + c * 32 + ak8;
        CP_ASYNC16(dst, src);
    };
    auto CONVW = [&](int s) {
        const float* raw = reinterpret_cast<const float*>(smem + RAW0 + s * RAWSZ);
        char* st = smem + s * STAGE;
        float pw[16];
#pragma unroll
        for (int r = 0; r < 16; r++) pw[r] = raw[(wkg * 16 + r) * 128 + wn];
        uint32_t hw[8];
#pragma unroll
        for (int r = 0; r < 8; r++) hw[r] = pack_h2(pw[2 * r], pw[2 * r + 1]);
        int bo = wn * (SA * 2) + wkg * 32;
        *reinterpret_cast<uint4*>(st + S_W + bo)      = make_uint4(hw[0], hw[1], hw[2], hw[3]);
        *reinterpret_cast<uint4*>(st + S_W + bo + 16) = make_uint4(hw[4], hw[5], hw[6], hw[7]);
    };
    auto MMA = [&](int s) {
        const uint32_t ab = sbase + s * STAGE;
        const uint32_t aB = ab + S_A + mw * (SA * 2) + aLaneOff;
        const uint32_t bB = ab + S_W + nwarp * (SA * 2) + bLaneOff;
#pragma unroll
        for (int ks = 0; ks < 2; ks++) {
            uint32_t ah[2][4];
#pragma unroll
            for (int mf = 0; mf < 2; mf++)
                ldsm_x4(ah[mf], aB + mf * (16 * SA * 2) + ks * 32);
#pragma unroll
            for (int np = 0; np < 2; np++) {
                uint32_t bh[4];
                ldsm_x4(bh, bB + np * (16 * SA * 2) + ks * 32);
#pragma unroll
                for (int mf = 0; mf < 2; mf++) {
                    float* c0 = acc + ((mf * 2 + np) * 2 + 0) * 4;
                    float* c1 = acc + ((mf * 2 + np) * 2 + 1) * 4;
                    mma16816(c0, ah[mf], bh[0], bh[1]);
                    mma16816(c1, ah[mf], bh[2], bh[3]);
                }
            }
        }
    };

    // prologue: chunk 0 (act+W) in group0, W(1) in group1
    AACT(0, 0); WASYNC(0, 0); CP_COMMIT();
    WASYNC(1, 1); CP_COMMIT();
    CP_WAIT1(); __syncthreads();
    CONVW(0);
    __syncthreads();
#pragma unroll 1
    for (int c = 0; c < CPK; c++) {
        if (c + 1 < CPK) AACT(c + 1, (c + 1) & 1);
        CP_COMMIT();
        if (c + 2 < CPK) WASYNC(c + 2, (c + 2) & 1);
        CP_COMMIT();
        MMA(c & 1);
        CP_WAIT1();
        __syncthreads();
        if (c + 1 < CPK) CONVW((c + 1) & 1);
        __syncthreads();
    }

    // epilogue: raw partial sums (bias added in reduce)
    const int gid = lane >> 2, tig = lane & 3;
    float* outT = Part + (size_t)kv * (BB * TT * DD) + (size_t)t * OTS + n0;
#pragma unroll
    for (int mf = 0; mf < 2; mf++)
#pragma unroll
        for (int np = 0; np < 2; np++)
#pragma unroll
            for (int atom = 0; atom < 2; atom++) {
                const float* a = acc + ((mf * 2 + np) * 2 + atom) * 4;
                int n = nwarp + np * 16 + atom * 8 + tig * 2;
                int m0 = mw + mf * 16 + gid;
                *reinterpret_cast<float2*>(outT + (size_t)m0 * OMS + n) =
                    make_float2(a[0], a[1]);
                *reinterpret_cast<float2*>(outT + (size_t)(m0 + 8) * OMS + n) =
                    make_float2(a[2], a[3]);
            }
}

// ═════════════ reduce: out = sum_kv part[kv] + bias ═════════════
__global__ void __launch_bounds__(256)
ffn_reduce(const float* __restrict__ Part, const float* __restrict__ bias,
           float* __restrict__ Out)
{
    constexpr size_t NQ = (size_t)BB * TT * DD / 4;
    constexpr uint32_t BMASK = (TT * DD / 4) - 1;
    size_t i = (size_t)blockIdx.x * 256 + threadIdx.x;
    const float4* p = reinterpret_cast<const float4*>(Part);
    float4 a = p[i];
    float4 b = p[i + NQ];
    float4 c = p[i + 2 * NQ];
    float4 d = p[i + 3 * NQ];
    float4 bv = reinterpret_cast<const float4*>(bias)[(uint32_t)i & BMASK];
    float4 o;
    o.x = a.x + b.x + c.x + d.x + bv.x;
    o.y = a.y + b.y + c.y + d.y + bv.y;
    o.z = a.z + b.z + c.z + d.z + bv.z;
    o.w = a.w + b.w + c.w + d.w + bv.w;
    reinterpret_cast<float4*>(Out)[i] = o;
}

// ───────────── host launcher ─────────────
extern "C" void kernel_launch(void* const* d_in, const int* in_sizes, int n_in,
                              void* d_out, int out_size)
{
    (void)in_sizes; (void)n_in; (void)out_size;
    const float* x  = (const float*)d_in[0];  // [B, T, D]
    const float* W1 = (const float*)d_in[1];  // [T, D, H]
    const float* b1 = (const float*)d_in[2];  // [T, H]
    const float* W2 = (const float*)d_in[3];  // [T, H, D]
    const float* b2 = (const float*)d_in[4];  // [T, D]
    float* out = (float*)d_out;               // [B, T, D]

    __half* h = nullptr;
    cudaGetSymbolAddress((void**)&h, g_h);
    float* part = nullptr;
    cudaGetSymbolAddress((void**)&part, g_part);

    cudaFuncSetAttribute(ffn_g1, cudaFuncAttributeMaxDynamicSharedMemorySize, SMEM_BYTES);
    ffn_g1<<<dim3(HH / 128, TT), NT, SMEM_BYTES>>>(W1, x, b1, h);

    cudaFuncSetAttribute(ffn_g2, cudaFuncAttributeMaxDynamicSharedMemorySize, SMEM_BYTES);
    ffn_g2<<<dim3(DD / 128, TT, NKV), NT, SMEM_BYTES>>>(W2, h, part);

    ffn_reduce<<<(BB * TT * DD / 4) / 256, 256>>>(part, b2, out);
}

// round 10
// speedup vs baseline: 2.2324x; 1.0088x over previous
#include <cuda_runtime.h>
#include <cuda_fp16.h>
#include <cstdint>
#include <math.h>

// Problem shape
#define BB 64
#define TT 128
#define DD 512
#define HH 2048

// h = gelu(x@W1+b1), fp16, layout [t][m][hidx] (32MB)
__device__ __half g_h[(size_t)TT * BB * HH];
// split-K partial sums for GEMM2: [kv][m][t][n] fp16 (32MB)
static constexpr int NKV = 4;
__device__ __half g_part[(size_t)NKV * BB * TT * DD];

static constexpr int SA = 40;   // padded SMEM row stride in fp16 (80 B, ldsm conflict-free)
static constexpr int NT = 256;  // 8 warps

// SMEM layout (bytes): two mma stages + two raw fp32 weight stages
static constexpr int S_A   = 0;      // act  [64 m][32 k] fp16 (5120)
static constexpr int S_W   = 5120;   // wgt  [128 n][32 k] fp16 (10240)
static constexpr int STAGE = 15360;
static constexpr int RAW0  = 2 * STAGE;   // 30720
static constexpr int RAWSZ = 16384;       // 32 k-rows x 128 n-cols fp32
static constexpr int SMEM_BYTES = RAW0 + 2 * RAWSZ;  // 63488

// ───────────── helpers ─────────────
__device__ __forceinline__ uint32_t smem_u32(const void* p) {
    uint32_t a;
    asm("{ .reg .u64 t; cvta.to.shared.u64 t, %1; cvt.u32.u64 %0, t; }" : "=r"(a) : "l"(p));
    return a;
}
#define CP_ASYNC16(dst, src) \
    asm volatile("cp.async.cg.shared.global [%0], [%1], 16;" :: "r"(dst), "l"(src) : "memory")
#define CP_COMMIT() asm volatile("cp.async.commit_group;" ::: "memory")
#define CP_WAIT1()  asm volatile("cp.async.wait_group 1;" ::: "memory")
#define CP_WAIT2()  asm volatile("cp.async.wait_group 2;" ::: "memory")

__device__ __forceinline__ void ldsm_x4(uint32_t* r, uint32_t addr) {
    asm volatile("ldmatrix.sync.aligned.m8n8.x4.shared.b16 {%0,%1,%2,%3}, [%4];"
                 : "=r"(r[0]), "=r"(r[1]), "=r"(r[2]), "=r"(r[3]) : "r"(addr));
}
__device__ __forceinline__ void mma16816(float* c, const uint32_t* a, uint32_t b0, uint32_t b1) {
    asm volatile("mma.sync.aligned.m16n8k16.row.col.f32.f16.f16.f32 "
                 "{%0,%1,%2,%3}, {%4,%5,%6,%7}, {%8,%9}, {%0,%1,%2,%3};"
                 : "+f"(c[0]), "+f"(c[1]), "+f"(c[2]), "+f"(c[3])
                 : "r"(a[0]), "r"(a[1]), "r"(a[2]), "r"(a[3]), "r"(b0), "r"(b1));
}
__device__ __forceinline__ uint32_t pack_h2(float x, float y) {
    __half2 t = __floats2half2_rn(x, y);
    return *reinterpret_cast<uint32_t*>(&t);
}
__device__ __forceinline__ float gelu_exact(float v) {
    return 0.5f * v * (1.0f + erff(v * 0.70710678118654752440f));
}

// ═════════════ GEMM1: x (fp32→fp16) @ W1 → gelu → h (fp16) ═════════════
__global__ void __launch_bounds__(NT)
ffn_g1(const float* __restrict__ W, const float* __restrict__ Act,
       const float* __restrict__ bias, __half* __restrict__ Out)
{
    constexpr int K = DD, NFULL = HH;
    constexpr int ATS = DD, AMS = TT * DD;        // x: [m][t][d]
    constexpr int OTS = BB * HH, OMS = HH;        // h: [t][m][n]
    extern __shared__ char smem[];
    const int t = blockIdx.y, n0 = blockIdx.x * 128;
    const int tid = threadIdx.x, wid = tid >> 5, lane = tid & 31;
    const uint32_t sbase = smem_u32(smem);

    const float* At = Act + (size_t)t * ATS;
    const float* Wt = W + (size_t)t * K * NFULL + n0;

    const int mw = (wid >> 2) * 32;
    const int nwarp = (wid & 3) * 32;
    const uint32_t aLaneOff = (uint32_t)(((lane & 15) * SA + (lane >> 4) * 8) * 2);
    const uint32_t bLaneOff = (uint32_t)(((((lane >> 4) << 3) + (lane & 7)) * SA +
                                          (((lane >> 3) & 1) * 8)) * 2);

    const int am = tid >> 2, ak8 = (tid & 3) * 8;  // act: 64 rows x 8 consecutive k
    const int wn = tid & 127, wkg = tid >> 7;      // convert: column, 16-row group

    float acc[32];
#pragma unroll
    for (int i = 0; i < 32; i++) acc[i] = 0.0f;

    float4 pa0, pa1;

    auto WASYNC = [&](int c, int s) {
        const float* base = Wt + (size_t)(c * 32) * NFULL;
        uint32_t dst = sbase + RAW0 + s * RAWSZ + tid * 16;
#pragma unroll
        for (int j = 0; j < 4; j++) {
            int o = tid + 256 * j;
            const float* src = base + (size_t)(o >> 5) * NFULL + (o & 31) * 4;
            CP_ASYNC16(dst + j * 4096, src);
        }
    };
    auto LOADX = [&](int c) {
        const float* ap = At + (size_t)am * AMS + c * 32 + ak8;
        pa0 = *reinterpret_cast<const float4*>(ap);
        pa1 = *reinterpret_cast<const float4*>(ap + 4);
    };
    auto STOREX = [&](int s) {
        char* st = smem + s * STAGE;
        uint4 av = make_uint4(pack_h2(pa0.x, pa0.y), pack_h2(pa0.z, pa0.w),
                              pack_h2(pa1.x, pa1.y), pack_h2(pa1.z, pa1.w));
        *reinterpret_cast<uint4*>(st + S_A + am * (SA * 2) + ak8 * 2) = av;
    };
    auto CONVW = [&](int s) {
        const float* raw = reinterpret_cast<const float*>(smem + RAW0 + s * RAWSZ);
        char* st = smem + s * STAGE;
        float pw[16];
#pragma unroll
        for (int r = 0; r < 16; r++) pw[r] = raw[(wkg * 16 + r) * 128 + wn];
        uint32_t hw[8];
#pragma unroll
        for (int r = 0; r < 8; r++) hw[r] = pack_h2(pw[2 * r], pw[2 * r + 1]);
        int bo = wn * (SA * 2) + wkg * 32;
        *reinterpret_cast<uint4*>(st + S_W + bo)      = make_uint4(hw[0], hw[1], hw[2], hw[3]);
        *reinterpret_cast<uint4*>(st + S_W + bo + 16) = make_uint4(hw[4], hw[5], hw[6], hw[7]);
    };
    auto MMA = [&](int s) {
        const uint32_t ab = sbase + s * STAGE;
        const uint32_t aB = ab + S_A + mw * (SA * 2) + aLaneOff;
        const uint32_t bB = ab + S_W + nwarp * (SA * 2) + bLaneOff;
#pragma unroll
        for (int ks = 0; ks < 2; ks++) {
            uint32_t ah[2][4];
#pragma unroll
            for (int mf = 0; mf < 2; mf++)
                ldsm_x4(ah[mf], aB + mf * (16 * SA * 2) + ks * 32);
#pragma unroll
            for (int np = 0; np < 2; np++) {
                uint32_t bh[4];
                ldsm_x4(bh, bB + np * (16 * SA * 2) + ks * 32);
#pragma unroll
                for (int mf = 0; mf < 2; mf++) {
                    float* c0 = acc + ((mf * 2 + np) * 2 + 0) * 4;
                    float* c1 = acc + ((mf * 2 + np) * 2 + 1) * 4;
                    mma16816(c0, ah[mf], bh[0], bh[1]);
                    mma16816(c1, ah[mf], bh[2], bh[3]);
                }
            }
        }
    };

    constexpr int NCHUNK = K / 32;
    // prologue: stage 0 ready (A + W), raw1 in flight
    WASYNC(0, 0); CP_COMMIT();
    WASYNC(1, 1); CP_COMMIT();
    LOADX(0);
    CP_WAIT1(); __syncthreads();
    STOREX(0); CONVW(0);
    __syncthreads();
#pragma unroll 1
    for (int c = 0; c < NCHUNK; c++) {
        if (c + 1 < NCHUNK) LOADX(c + 1);          // LDG early, latency spans wait+bar
        if (c + 2 < NCHUNK) WASYNC(c + 2, c & 1);  // raw c&1 last read prev window (bar'd)
        CP_COMMIT();
        CP_WAIT1();                                 // raw(c+1) arrived
        __syncthreads();                            // cross-thread visibility
        // merged window: convert/stage (c+1) interleaved with MMA(c)
        if (c + 1 < NCHUNK) { CONVW((c + 1) & 1); STOREX((c + 1) & 1); }
        MMA(c & 1);
        __syncthreads();                            // stage (c+1) visible for next MMA
    }

    // epilogue: bias + exact GELU → fp16 h
    const int gid = lane >> 2, tig = lane & 3;
    const float* bt = bias + (size_t)t * NFULL + n0;
    __half* outT = Out + (size_t)t * OTS + n0;
#pragma unroll
    for (int mf = 0; mf < 2; mf++)
#pragma unroll
        for (int np = 0; np < 2; np++)
#pragma unroll
            for (int atom = 0; atom < 2; atom++) {
                const float* a = acc + ((mf * 2 + np) * 2 + atom) * 4;
                int n = nwarp + np * 16 + atom * 8 + tig * 2;
                float bv0 = bt[n], bv1 = bt[n + 1];
                int m0 = mw + mf * 16 + gid;
                *reinterpret_cast<__half2*>(outT + (size_t)m0 * OMS + n) =
                    __floats2half2_rn(gelu_exact(a[0] + bv0), gelu_exact(a[1] + bv1));
                *reinterpret_cast<__half2*>(outT + (size_t)(m0 + 8) * OMS + n) =
                    __floats2half2_rn(gelu_exact(a[2] + bv0), gelu_exact(a[3] + bv1));
            }
}

// ═════════════ GEMM2: h (fp16, cp.async) @ W2, split-K=4 → fp16 partials ═════════════
__global__ void __launch_bounds__(NT)
ffn_g2(const float* __restrict__ W, const __half* __restrict__ Act,
       __half* __restrict__ Part)
{
    constexpr int K = HH, NFULL = DD;
    constexpr int ATS = BB * HH, AMS = HH;        // h: [t][m][k]
    constexpr int OTS = DD, OMS = TT * DD;        // partial: [kv][m][t][n]
    constexpr int CPK = (K / 32) / NKV;           // 16 chunks per K-piece
    extern __shared__ char smem[];
    const int t = blockIdx.y, n0 = blockIdx.x * 128;
    const int kv = blockIdx.z;
    const int tid = threadIdx.x, wid = tid >> 5, lane = tid & 31;
    const uint32_t sbase = smem_u32(smem);

    const __half* At = Act + (size_t)t * ATS + kv * (CPK * 32);
    const float* Wt = W + (size_t)t * K * NFULL + (size_t)(kv * CPK * 32) * NFULL + n0;

    const int mw = (wid >> 2) * 32;
    const int nwarp = (wid & 3) * 32;
    const uint32_t aLaneOff = (uint32_t)(((lane & 15) * SA + (lane >> 4) * 8) * 2);
    const uint32_t bLaneOff = (uint32_t)(((((lane >> 4) << 3) + (lane & 7)) * SA +
                                          (((lane >> 3) & 1) * 8)) * 2);

    const int am = tid >> 2, ak8 = (tid & 3) * 8;
    const int wn = tid & 127, wkg = tid >> 7;

    float acc[32];
#pragma unroll
    for (int i = 0; i < 32; i++) acc[i] = 0.0f;

    auto WASYNC = [&](int c, int s) {
        const float* base = Wt + (size_t)(c * 32) * NFULL;
        uint32_t dst = sbase + RAW0 + s * RAWSZ + tid * 16;
#pragma unroll
        for (int j = 0; j < 4; j++) {
            int o = tid + 256 * j;
            const float* src = base + (size_t)(o >> 5) * NFULL + (o & 31) * 4;
            CP_ASYNC16(dst + j * 4096, src);
        }
    };
    auto AACT = [&](int c, int s) {
        uint32_t dst = sbase + s * STAGE + S_A + am * (SA * 2) + ak8 * 2;
        const __half* src = At + (size_t)am * AMS + c * 32 + ak8;
        CP_ASYNC16(dst, src);
    };
    auto CONVW = [&](int s) {
        const float* raw = reinterpret_cast<const float*>(smem + RAW0 + s * RAWSZ);
        char* st = smem + s * STAGE;
        float pw[16];
#pragma unroll
        for (int r = 0; r < 16; r++) pw[r] = raw[(wkg * 16 + r) * 128 + wn];
        uint32_t hw[8];
#pragma unroll
        for (int r = 0; r < 8; r++) hw[r] = pack_h2(pw[2 * r], pw[2 * r + 1]);
        int bo = wn * (SA * 2) + wkg * 32;
        *reinterpret_cast<uint4*>(st + S_W + bo)      = make_uint4(hw[0], hw[1], hw[2], hw[3]);
        *reinterpret_cast<uint4*>(st + S_W + bo + 16) = make_uint4(hw[4], hw[5], hw[6], hw[7]);
    };
    auto MMA = [&](int s) {
        const uint32_t ab = sbase + s * STAGE;
        const uint32_t aB = ab + S_A + mw * (SA * 2) + aLaneOff;
        const uint32_t bB = ab + S_W + nwarp * (SA * 2) + bLaneOff;
#pragma unroll
        for (int ks = 0; ks < 2; ks++) {
            uint32_t ah[2][4];
#pragma unroll
            for (int mf = 0; mf < 2; mf++)
                ldsm_x4(ah[mf], aB + mf * (16 * SA * 2) + ks * 32);
#pragma unroll
            for (int np = 0; np < 2; np++) {
                uint32_t bh[4];
                ldsm_x4(bh, bB + np * (16 * SA * 2) + ks * 32);
#pragma unroll
                for (int mf = 0; mf < 2; mf++) {
                    float* c0 = acc + ((mf * 2 + np) * 2 + 0) * 4;
                    float* c1 = acc + ((mf * 2 + np) * 2 + 1) * 4;
                    mma16816(c0, ah[mf], bh[0], bh[1]);
                    mma16816(c1, ah[mf], bh[2], bh[3]);
                }
            }
        }
    };

    // prologue: act0+W0 (G0), W1 (G1); stage 0 W converted
    AACT(0, 0); WASYNC(0, 0); CP_COMMIT();
    WASYNC(1, 1); CP_COMMIT();
    CP_WAIT1(); __syncthreads();
    CONVW(0);
    __syncthreads();
#pragma unroll 1
    for (int c = 0; c < CPK; c++) {
        if (c + 1 < CPK) AACT(c + 1, (c + 1) & 1);   // A stage (c+1): last read MMA(c-1), bar'd
        CP_COMMIT();                                  // group: act(c+1)
        if (c + 2 < CPK) WASYNC(c + 2, c & 1);        // raw c&1: last read CONVW(c), bar'd
        CP_COMMIT();                                  // group: W(c+2)
        CP_WAIT2();                                   // act(c) + raw(c+1) complete
        __syncthreads();
        if (c + 1 < CPK) CONVW((c + 1) & 1);          // overlaps MMA below
        MMA(c & 1);
        __syncthreads();
    }

    // epilogue: fp16 raw partial sums (bias added in reduce)
    const int gid = lane >> 2, tig = lane & 3;
    __half* outT = Part + (size_t)kv * (BB * TT * DD) + (size_t)t * OTS + n0;
#pragma unroll
    for (int mf = 0; mf < 2; mf++)
#pragma unroll
        for (int np = 0; np < 2; np++)
#pragma unroll
            for (int atom = 0; atom < 2; atom++) {
                const float* a = acc + ((mf * 2 + np) * 2 + atom) * 4;
                int n = nwarp + np * 16 + atom * 8 + tig * 2;
                int m0 = mw + mf * 16 + gid;
                *reinterpret_cast<__half2*>(outT + (size_t)m0 * OMS + n) =
                    __floats2half2_rn(a[0], a[1]);
                *reinterpret_cast<__half2*>(outT + (size_t)(m0 + 8) * OMS + n) =
                    __floats2half2_rn(a[2], a[3]);
            }
}

// ═════════════ reduce: out = sum_kv part[kv] + bias (8 elems/thread) ═════════════
__global__ void __launch_bounds__(256)
ffn_reduce(const __half* __restrict__ Part, const float* __restrict__ bias,
           float* __restrict__ Out)
{
    constexpr size_t N8 = (size_t)BB * TT * DD / 8;       // half8 groups
    constexpr uint32_t BMASK8 = (TT * DD / 8) - 1;
    size_t i = (size_t)blockIdx.x * 256 + threadIdx.x;
    const uint4* p = reinterpret_cast<const uint4*>(Part);
    float s[8];
#pragma unroll
    for (int j = 0; j < 8; j++) s[j] = 0.0f;
#pragma unroll
    for (int kv = 0; kv < NKV; kv++) {
        uint4 v = p[i + kv * N8];
        const uint32_t w[4] = {v.x, v.y, v.z, v.w};
#pragma unroll
        for (int j = 0; j < 4; j++) {
            __half2 h2 = *reinterpret_cast<const __half2*>(&w[j]);
            float2 f = __half22float2(h2);
            s[2 * j] += f.x;
            s[2 * j + 1] += f.y;
        }
    }
    uint32_t b4 = ((uint32_t)i & BMASK8) * 2;
    float4 bv0 = reinterpret_cast<const float4*>(bias)[b4];
    float4 bv1 = reinterpret_cast<const float4*>(bias)[b4 + 1];
    float4 o0 = make_float4(s[0] + bv0.x, s[1] + bv0.y, s[2] + bv0.z, s[3] + bv0.w);
    float4 o1 = make_float4(s[4] + bv1.x, s[5] + bv1.y, s[6] + bv1.z, s[7] + bv1.w);
    reinterpret_cast<float4*>(Out)[2 * i]     = o0;
    reinterpret_cast<float4*>(Out)[2 * i + 1] = o1;
}

// ───────────── host launcher ─────────────
extern "C" void kernel_launch(void* const* d_in, const int* in_sizes, int n_in,
                              void* d_out, int out_size)
{
    (void)in_sizes; (void)n_in; (void)out_size;
    const float* x  = (const float*)d_in[0];  // [B, T, D]
    const float* W1 = (const float*)d_in[1];  // [T, D, H]
    const float* b1 = (const float*)d_in[2];  // [T, H]
    const float* W2 = (const float*)d_in[3];  // [T, H, D]
    const float* b2 = (const float*)d_in[4];  // [T, D]
    float* out = (float*)d_out;               // [B, T, D]

    __half* h = nullptr;
    cudaGetSymbolAddress((void**)&h, g_h);
    __half* part = nullptr;
    cudaGetSymbolAddress((void**)&part, g_part);

    cudaFuncSetAttribute(ffn_g1, cudaFuncAttributeMaxDynamicSharedMemorySize, SMEM_BYTES);
    ffn_g1<<<dim3(HH / 128, TT), NT, SMEM_BYTES>>>(W1, x, b1, h);

    cudaFuncSetAttribute(ffn_g2, cudaFuncAttributeMaxDynamicSharedMemorySize, SMEM_BYTES);
    ffn_g2<<<dim3(DD / 128, TT, NKV), NT, SMEM_BYTES>>>(W2, h, part);

    ffn_reduce<<<(BB * TT * DD / 8) / 256, 256>>>(part, b2, out);
}

// round 11
// speedup vs baseline: 2.2495x; 1.0077x over previous
#include <cuda_runtime.h>
#include <cuda_fp16.h>
#include <cstdint>
#include <math.h>

// Problem shape
#define BB 64
#define TT 128
#define DD 512
#define HH 2048

// h = gelu(x@W1+b1), fp16, layout [t][m][hidx] (32MB)
__device__ __half g_h[(size_t)TT * BB * HH];
// split-K partial sums for GEMM2: [kv][m][t][n] fp16 (32MB)
static constexpr int NKV = 4;
__device__ __half g_part[(size_t)NKV * BB * TT * DD];

static constexpr int SA = 40;   // padded SMEM row stride in fp16 (80 B, ldsm conflict-free)
static constexpr int NT = 256;  // 8 warps

// SMEM layout (bytes): two mma stages + two raw fp32 weight stages
static constexpr int S_A   = 0;      // act  [64 m][32 k] fp16 (5120)
static constexpr int S_W   = 5120;   // wgt  [128 n][32 k] fp16 (10240)
static constexpr int STAGE = 15360;
static constexpr int RAW0  = 2 * STAGE;   // 30720
static constexpr int RAWSZ = 16384;       // 32 k-rows x 128 n-cols fp32
static constexpr int SMEM_BYTES = RAW0 + 2 * RAWSZ;  // 63488

// ───────────── helpers ─────────────
__device__ __forceinline__ uint32_t smem_u32(const void* p) {
    uint32_t a;
    asm("{ .reg .u64 t; cvta.to.shared.u64 t, %1; cvt.u32.u64 %0, t; }" : "=r"(a) : "l"(p));
    return a;
}
#define CP_ASYNC16(dst, src) \
    asm volatile("cp.async.cg.shared.global [%0], [%1], 16;" :: "r"(dst), "l"(src) : "memory")
#define CP_COMMIT() asm volatile("cp.async.commit_group;" ::: "memory")
#define CP_WAIT1()  asm volatile("cp.async.wait_group 1;" ::: "memory")

__device__ __forceinline__ void ldsm_x4(uint32_t* r, uint32_t addr) {
    asm volatile("ldmatrix.sync.aligned.m8n8.x4.shared.b16 {%0,%1,%2,%3}, [%4];"
                 : "=r"(r[0]), "=r"(r[1]), "=r"(r[2]), "=r"(r[3]) : "r"(addr));
}
__device__ __forceinline__ void mma16816(float* c, const uint32_t* a, uint32_t b0, uint32_t b1) {
    asm volatile("mma.sync.aligned.m16n8k16.row.col.f32.f16.f16.f32 "
                 "{%0,%1,%2,%3}, {%4,%5,%6,%7}, {%8,%9}, {%0,%1,%2,%3};"
                 : "+f"(c[0]), "+f"(c[1]), "+f"(c[2]), "+f"(c[3])
                 : "r"(a[0]), "r"(a[1]), "r"(a[2]), "r"(a[3]), "r"(b0), "r"(b1));
}
__device__ __forceinline__ uint32_t pack_h2(float x, float y) {
    __half2 t = __floats2half2_rn(x, y);
    return *reinterpret_cast<uint32_t*>(&t);
}
__device__ __forceinline__ float gelu_exact(float v) {
    return 0.5f * v * (1.0f + erff(v * 0.70710678118654752440f));
}

// ═════════════ GEMM1: x (fp32→fp16) @ W1 → gelu → h (fp16) ═════════════
__global__ void __launch_bounds__(NT)
ffn_g1(const float* __restrict__ W, const float* __restrict__ Act,
       const float* __restrict__ bias, __half* __restrict__ Out)
{
    constexpr int K = DD, NFULL = HH;
    constexpr int ATS = DD, AMS = TT * DD;        // x: [m][t][d]
    constexpr int OTS = BB * HH, OMS = HH;        // h: [t][m][n]
    extern __shared__ char smem[];
    const int t = blockIdx.y, n0 = blockIdx.x * 128;
    const int tid = threadIdx.x, wid = tid >> 5, lane = tid & 31;
    const uint32_t sbase = smem_u32(smem);

    const float* At = Act + (size_t)t * ATS;
    const float* Wt = W + (size_t)t * K * NFULL + n0;

    const int mw = (wid >> 2) * 32;
    const int nwarp = (wid & 3) * 32;
    const uint32_t aLaneOff = (uint32_t)(((lane & 15) * SA + (lane >> 4) * 8) * 2);
    const uint32_t bLaneOff = (uint32_t)(((((lane >> 4) << 3) + (lane & 7)) * SA +
                                          (((lane >> 3) & 1) * 8)) * 2);

    const int am = tid >> 2, ak8 = (tid & 3) * 8;  // act: 64 rows x 8 consecutive k
    const int wn = tid & 127, wkg = tid >> 7;      // convert: column, 16-row group

    float acc[32];
#pragma unroll
    for (int i = 0; i < 32; i++) acc[i] = 0.0f;

    float4 pa0, pa1;

    auto WASYNC = [&](int c, int s) {
        const float* base = Wt + (size_t)(c * 32) * NFULL;
        uint32_t dst = sbase + RAW0 + s * RAWSZ + tid * 16;
#pragma unroll
        for (int j = 0; j < 4; j++) {
            int o = tid + 256 * j;
            const float* src = base + (size_t)(o >> 5) * NFULL + (o & 31) * 4;
            CP_ASYNC16(dst + j * 4096, src);
        }
    };
    auto LOADX = [&](int c) {
        const float* ap = At + (size_t)am * AMS + c * 32 + ak8;
        pa0 = *reinterpret_cast<const float4*>(ap);
        pa1 = *reinterpret_cast<const float4*>(ap + 4);
    };
    auto STOREX = [&](int s) {
        char* st = smem + s * STAGE;
        uint4 av = make_uint4(pack_h2(pa0.x, pa0.y), pack_h2(pa0.z, pa0.w),
                              pack_h2(pa1.x, pa1.y), pack_h2(pa1.z, pa1.w));
        *reinterpret_cast<uint4*>(st + S_A + am * (SA * 2) + ak8 * 2) = av;
    };
    auto CONVW = [&](int s) {
        const float* raw = reinterpret_cast<const float*>(smem + RAW0 + s * RAWSZ);
        char* st = smem + s * STAGE;
        float pw[16];
#pragma unroll
        for (int r = 0; r < 16; r++) pw[r] = raw[(wkg * 16 + r) * 128 + wn];
        uint32_t hw[8];
#pragma unroll
        for (int r = 0; r < 8; r++) hw[r] = pack_h2(pw[2 * r], pw[2 * r + 1]);
        int bo = wn * (SA * 2) + wkg * 32;
        *reinterpret_cast<uint4*>(st + S_W + bo)      = make_uint4(hw[0], hw[1], hw[2], hw[3]);
        *reinterpret_cast<uint4*>(st + S_W + bo + 16) = make_uint4(hw[4], hw[5], hw[6], hw[7]);
    };
    auto MMA = [&](int s) {
        const uint32_t ab = sbase + s * STAGE;
        const uint32_t aB = ab + S_A + mw * (SA * 2) + aLaneOff;
        const uint32_t bB = ab + S_W + nwarp * (SA * 2) + bLaneOff;
#pragma unroll
        for (int ks = 0; ks < 2; ks++) {
            uint32_t ah[2][4];
#pragma unroll
            for (int mf = 0; mf < 2; mf++)
                ldsm_x4(ah[mf], aB + mf * (16 * SA * 2) + ks * 32);
#pragma unroll
            for (int np = 0; np < 2; np++) {
                uint32_t bh[4];
                ldsm_x4(bh, bB + np * (16 * SA * 2) + ks * 32);
#pragma unroll
                for (int mf = 0; mf < 2; mf++) {
                    float* c0 = acc + ((mf * 2 + np) * 2 + 0) * 4;
                    float* c1 = acc + ((mf * 2 + np) * 2 + 1) * 4;
                    mma16816(c0, ah[mf], bh[0], bh[1]);
                    mma16816(c1, ah[mf], bh[2], bh[3]);
                }
            }
        }
    };

    constexpr int NCHUNK = K / 32;
    // prologue: stage 0 ready (A + W), raw1 in flight
    WASYNC(0, 0); CP_COMMIT();
    WASYNC(1, 1); CP_COMMIT();
    LOADX(0);
    CP_WAIT1(); __syncthreads();
    STOREX(0); CONVW(0);
    __syncthreads();
#pragma unroll 1
    for (int c = 0; c < NCHUNK; c++) {
        if (c + 1 < NCHUNK) LOADX(c + 1);          // LDG latency hidden behind MMAs
        if (c + 2 < NCHUNK) WASYNC(c + 2, c & 1);  // raw c&1 last read by CONVW(c) (bar'd)
        CP_COMMIT();
        MMA(c & 1);                                 // runs while cp.async drains
        CP_WAIT1();                                 // raw(c+1) arrived
        __syncthreads();
        if (c + 1 < NCHUNK) { STOREX((c + 1) & 1); CONVW((c + 1) & 1); }
        __syncthreads();
    }

    // epilogue: bias + exact GELU → fp16 h
    const int gid = lane >> 2, tig = lane & 3;
    const float* bt = bias + (size_t)t * NFULL + n0;
    __half* outT = Out + (size_t)t * OTS + n0;
#pragma unroll
    for (int mf = 0; mf < 2; mf++)
#pragma unroll
        for (int np = 0; np < 2; np++)
#pragma unroll
            for (int atom = 0; atom < 2; atom++) {
                const float* a = acc + ((mf * 2 + np) * 2 + atom) * 4;
                int n = nwarp + np * 16 + atom * 8 + tig * 2;
                float bv0 = bt[n], bv1 = bt[n + 1];
                int m0 = mw + mf * 16 + gid;
                *reinterpret_cast<__half2*>(outT + (size_t)m0 * OMS + n) =
                    __floats2half2_rn(gelu_exact(a[0] + bv0), gelu_exact(a[1] + bv1));
                *reinterpret_cast<__half2*>(outT + (size_t)(m0 + 8) * OMS + n) =
                    __floats2half2_rn(gelu_exact(a[2] + bv0), gelu_exact(a[3] + bv1));
            }
}

// ═════════════ GEMM2: h (fp16, cp.async) @ W2, split-K=4 → fp16 partials ═════════════
__global__ void __launch_bounds__(NT)
ffn_g2(const float* __restrict__ W, const __half* __restrict__ Act,
       __half* __restrict__ Part)
{
    constexpr int K = HH, NFULL = DD;
    constexpr int ATS = BB * HH, AMS = HH;        // h: [t][m][k]
    constexpr int OTS = DD, OMS = TT * DD;        // partial: [kv][m][t][n]
    constexpr int CPK = (K / 32) / NKV;           // 16 chunks per K-piece
    extern __shared__ char smem[];
    const int t = blockIdx.y, n0 = blockIdx.x * 128;
    const int kv = blockIdx.z;
    const int tid = threadIdx.x, wid = tid >> 5, lane = tid & 31;
    const uint32_t sbase = smem_u32(smem);

    const __half* At = Act + (size_t)t * ATS + kv * (CPK * 32);
    const float* Wt = W + (size_t)t * K * NFULL + (size_t)(kv * CPK * 32) * NFULL + n0;

    const int mw = (wid >> 2) * 32;
    const int nwarp = (wid & 3) * 32;
    const uint32_t aLaneOff = (uint32_t)(((lane & 15) * SA + (lane >> 4) * 8) * 2);
    const uint32_t bLaneOff = (uint32_t)(((((lane >> 4) << 3) + (lane & 7)) * SA +
                                          (((lane >> 3) & 1) * 8)) * 2);

    const int am = tid >> 2, ak8 = (tid & 3) * 8;
    const int wn = tid & 127, wkg = tid >> 7;

    float acc[32];
#pragma unroll
    for (int i = 0; i < 32; i++) acc[i] = 0.0f;

    auto WASYNC = [&](int c, int s) {
        const float* base = Wt + (size_t)(c * 32) * NFULL;
        uint32_t dst = sbase + RAW0 + s * RAWSZ + tid * 16;
#pragma unroll
        for (int j = 0; j < 4; j++) {
            int o = tid + 256 * j;
            const float* src = base + (size_t)(o >> 5) * NFULL + (o & 31) * 4;
            CP_ASYNC16(dst + j * 4096, src);
        }
    };
    auto AACT = [&](int c, int s) {
        uint32_t dst = sbase + s * STAGE + S_A + am * (SA * 2) + ak8 * 2;
        const __half* src = At + (size_t)am * AMS + c * 32 + ak8;
        CP_ASYNC16(dst, src);
    };
    auto CONVW = [&](int s) {
        const float* raw = reinterpret_cast<const float*>(smem + RAW0 + s * RAWSZ);
        char* st = smem + s * STAGE;
        float pw[16];
#pragma unroll
        for (int r = 0; r < 16; r++) pw[r] = raw[(wkg * 16 + r) * 128 + wn];
        uint32_t hw[8];
#pragma unroll
        for (int r = 0; r < 8; r++) hw[r] = pack_h2(pw[2 * r], pw[2 * r + 1]);
        int bo = wn * (SA * 2) + wkg * 32;
        *reinterpret_cast<uint4*>(st + S_W + bo)      = make_uint4(hw[0], hw[1], hw[2], hw[3]);
        *reinterpret_cast<uint4*>(st + S_W + bo + 16) = make_uint4(hw[4], hw[5], hw[6], hw[7]);
    };
    auto MMA = [&](int s) {
        const uint32_t ab = sbase + s * STAGE;
        const uint32_t aB = ab + S_A + mw * (SA * 2) + aLaneOff;
        const uint32_t bB = ab + S_W + nwarp * (SA * 2) + bLaneOff;
#pragma unroll
        for (int ks = 0; ks < 2; ks++) {
            uint32_t ah[2][4];
#pragma unroll
            for (int mf = 0; mf < 2; mf++)
                ldsm_x4(ah[mf], aB + mf * (16 * SA * 2) + ks * 32);
#pragma unroll
            for (int np = 0; np < 2; np++) {
                uint32_t bh[4];
                ldsm_x4(bh, bB + np * (16 * SA * 2) + ks * 32);
#pragma unroll
                for (int mf = 0; mf < 2; mf++) {
                    float* c0 = acc + ((mf * 2 + np) * 2 + 0) * 4;
                    float* c1 = acc + ((mf * 2 + np) * 2 + 1) * 4;
                    mma16816(c0, ah[mf], bh[0], bh[1]);
                    mma16816(c1, ah[mf], bh[2], bh[3]);
                }
            }
        }
    };

    // prologue: act0+W0 (G0), W1 (G1); stage 0 W converted
    AACT(0, 0); WASYNC(0, 0); CP_COMMIT();
    WASYNC(1, 1); CP_COMMIT();
    CP_WAIT1(); __syncthreads();
    CONVW(0);
    __syncthreads();
#pragma unroll 1
    for (int c = 0; c < CPK; c++) {
        if (c + 1 < CPK) AACT(c + 1, (c + 1) & 1);   // A stage (c+1): last read MMA(c-1), bar'd
        CP_COMMIT();                                  // group: act(c+1)
        if (c + 2 < CPK) WASYNC(c + 2, c & 1);        // raw c&1: last read CONVW(c), bar'd
        CP_COMMIT();                                  // group: W(c+2)
        MMA(c & 1);                                   // runs while cp.async drains
        CP_WAIT1();                                   // act(c+1) + raw(c+1) complete
        __syncthreads();
        if (c + 1 < CPK) CONVW((c + 1) & 1);
        __syncthreads();
    }

    // epilogue: fp16 raw partial sums (bias added in reduce)
    const int gid = lane >> 2, tig = lane & 3;
    __half* outT = Part + (size_t)kv * (BB * TT * DD) + (size_t)t * OTS + n0;
#pragma unroll
    for (int mf = 0; mf < 2; mf++)
#pragma unroll
        for (int np = 0; np < 2; np++)
#pragma unroll
            for (int atom = 0; atom < 2; atom++) {
                const float* a = acc + ((mf * 2 + np) * 2 + atom) * 4;
                int n = nwarp + np * 16 + atom * 8 + tig * 2;
                int m0 = mw + mf * 16 + gid;
                *reinterpret_cast<__half2*>(outT + (size_t)m0 * OMS + n) =
                    __floats2half2_rn(a[0], a[1]);
                *reinterpret_cast<__half2*>(outT + (size_t)(m0 + 8) * OMS + n) =
                    __floats2half2_rn(a[2], a[3]);
            }
}

// ═════════════ reduce: out = sum_kv part[kv] + bias (8 elems/thread) ═════════════
__global__ void __launch_bounds__(256)
ffn_reduce(const __half* __restrict__ Part, const float* __restrict__ bias,
           float* __restrict__ Out)
{
    constexpr size_t N8 = (size_t)BB * TT * DD / 8;       // half8 groups
    constexpr uint32_t BMASK8 = (TT * DD / 8) - 1;
    size_t i = (size_t)blockIdx.x * 256 + threadIdx.x;
    const uint4* p = reinterpret_cast<const uint4*>(Part);
    float s[8];
#pragma unroll
    for (int j = 0; j < 8; j++) s[j] = 0.0f;
#pragma unroll
    for (int kv = 0; kv < NKV; kv++) {
        uint4 v = p[i + kv * N8];
        const uint32_t w[4] = {v.x, v.y, v.z, v.w};
#pragma unroll
        for (int j = 0; j < 4; j++) {
            __half2 h2 = *reinterpret_cast<const __half2*>(&w[j]);
            float2 f = __half22float2(h2);
            s[2 * j] += f.x;
            s[2 * j + 1] += f.y;
        }
    }
    uint32_t b4 = ((uint32_t)i & BMASK8) * 2;
    float4 bv0 = reinterpret_cast<const float4*>(bias)[b4];
    float4 bv1 = reinterpret_cast<const float4*>(bias)[b4 + 1];
    float4 o0 = make_float4(s[0] + bv0.x, s[1] + bv0.y, s[2] + bv0.z, s[3] + bv0.w);
    float4 o1 = make_float4(s[4] + bv1.x, s[5] + bv1.y, s[6] + bv1.z, s[7] + bv1.w);
    reinterpret_cast<float4*>(Out)[2 * i]     = o0;
    reinterpret_cast<float4*>(Out)[2 * i + 1] = o1;
}

// ───────────── host launcher ─────────────
extern "C" void kernel_launch(void* const* d_in, const int* in_sizes, int n_in,
                              void* d_out, int out_size)
{
    (void)in_sizes; (void)n_in; (void)out_size;
    const float* x  = (const float*)d_in[0];  // [B, T, D]
    const float* W1 = (const float*)d_in[1];  // [T, D, H]
    const float* b1 = (const float*)d_in[2];  // [T, H]
    const float* W2 = (const float*)d_in[3];  // [T, H, D]
    const float* b2 = (const float*)d_in[4];  // [T, D]
    float* out = (float*)d_out;               // [B, T, D]

    __half* h = nullptr;
    cudaGetSymbolAddress((void**)&h, g_h);
    __half* part = nullptr;
    cudaGetSymbolAddress((void**)&part, g_part);

    cudaFuncSetAttribute(ffn_g1, cudaFuncAttributeMaxDynamicSharedMemorySize, SMEM_BYTES);
    ffn_g1<<<dim3(HH / 128, TT), NT, SMEM_BYTES>>>(W1, x, b1, h);

    cudaFuncSetAttribute(ffn_g2, cudaFuncAttributeMaxDynamicSharedMemorySize, SMEM_BYTES);
    ffn_g2<<<dim3(DD / 128, TT, NKV), NT, SMEM_BYTES>>>(W2, h, part);

    ffn_reduce<<<(BB * TT * DD / 8) / 256, 256>>>(part, b2, out);
}